// round 4
// baseline (speedup 1.0000x reference)
#include <cuda_runtime.h>
#include <math.h>
#include <stdint.h>

// Problem constants
#define L_  6
#define B_  16
#define T_  2048
#define D_  768
#define V_  50280
#define R_  96               // L_*B_ rows
#define PW  1572             // ceil(V_/32) bitmap words per batch row
#define NTILE 128            // vocab tile per block
#define NT  393              // ceil(V_/NTILE)
#define KB  16               // K chunk
#define NCHUNK (D_ / KB)     // 48

typedef unsigned long long ull;

// -------- device scratch (no allocations allowed) --------
__device__ unsigned int g_present[B_ * PW];
__device__ float g_h[R_ * D_];
__device__ float g_pm[NT * R_];
__device__ float g_ps[NT * R_];
__device__ int   g_pi[NT * R_];
__device__ float g_rownll[R_];
__device__ float g_rowacc[R_];
__device__ int   g_rowvalid[R_];

// -------- packed f32x2 FMA --------
#define FMA2(acc, a, b) \
    asm("fma.rn.f32x2 %0, %1, %2, %0;" : "+l"(acc) : "l"(a), "l"(b))

__device__ __forceinline__ float2 unpack2(ull v) {
    float2 f;
    f.x = __uint_as_float((unsigned)(v & 0xffffffffull));
    f.y = __uint_as_float((unsigned)(v >> 32));
    return f;
}

// online-softmax + first-occurrence-argmax merge
__device__ __forceinline__ void sm_combine(float& m, float& s, int& bi,
                                           float m2, float s2, int bi2) {
    if (m2 > m) {
        s = s * __expf(m - m2) + s2;
        m = m2;
        bi = bi2;
    } else if (m2 == m) {
        s += s2;
        if (bi2 < bi) bi = bi2;
    } else {
        s += s2 * __expf(m2 - m);
    }
}

// -------- small kernels --------
__global__ void zero_present_kernel() {
    int i = blockIdx.x * blockDim.x + threadIdx.x;
    if (i < B_ * PW) g_present[i] = 0u;
}

__global__ void scatter_kernel(const int* __restrict__ ids) {
    int i = blockIdx.x * blockDim.x + threadIdx.x;
    if (i < B_ * T_) {
        int b = i / T_;
        int tok = ids[i];
        if (tok >= 0 && tok < V_)
            atomicOr(&g_present[b * PW + (tok >> 5)], 1u << (tok & 31));
    }
}

__global__ void gather_kernel(const float* __restrict__ x,
                              const int* __restrict__ astarts) {
    int r = blockIdx.x;                 // r = l*B_ + b
    int b = r & (B_ - 1);
    int tt = astarts[b] - 1;
    if (tt < 0) tt = 0;
    if (tt >= T_) tt = T_ - 1;
    size_t base = ((size_t)r * T_ + (size_t)tt) * D_;
    for (int d = threadIdx.x; d < D_; d += blockDim.x)
        g_h[r * D_ + d] = x[base + d];
}

// ---------------- GEMM ----------------
// 96 rows x 128-vocab tile, K=768, fused mask + online softmax + argmax.
// Block: 192 threads = 16 vocab-threads (x8 v) * 12 row-threads (x8 rows).
// h stored DUPLICATED in smem (float2{h,h}) -> LDS.128 gives packed operands,
// no MOVs before FMA2. W chunk staged through registers (software pipeline).
__global__ void __launch_bounds__(192, 3) gemm_kernel(const float* __restrict__ w) {
    __shared__ __align__(16) float  wsm[KB][NTILE];   // 8 KB   [kk][v_local]
    __shared__ __align__(16) float2 hsm[KB][R_];      // 12 KB  [kk][row] duplicated

    const int tile  = blockIdx.x;
    const int vbase = tile * NTILE;
    const int t  = threadIdx.x;
    const int vt = t & 15;              // 0..15
    const int rt = t >> 4;              // 0..11

    // ---- staging registers ----
    // W chunk: 128 vocab x 16 k = 512 float4; 192 threads -> up to 3 each
    // H chunk: 96 rows x 16 k = 384 float4; 192 threads -> exactly 2 each
    float4 wst[3], hst[2];

    ull acc[8][4];
#pragma unroll
    for (int i = 0; i < 8; i++)
#pragma unroll
        for (int j = 0; j < 4; j++) acc[i][j] = 0ull;

    // prologue: load chunk 0 into stage regs
    {
        const int k0 = 0;
#pragma unroll
        for (int i = 0; i < 3; i++) {
            int idx = t + i * 192;
            if (idx < 512) {
                int vl = idx & 127, q = idx >> 7;
                int v = vbase + vl;
                wst[i] = (v < V_) ? *reinterpret_cast<const float4*>(w + (size_t)v * D_ + k0 + q * 4)
                                  : make_float4(0.f, 0.f, 0.f, 0.f);
            }
        }
#pragma unroll
        for (int i = 0; i < 2; i++) {
            int idx = t + i * 192;
            int r = idx % R_, q = idx / R_;
            hst[i] = *reinterpret_cast<const float4*>(g_h + r * D_ + k0 + q * 4);
        }
    }

    for (int c = 0; c < NCHUNK; c++) {
        __syncthreads();                 // previous compute finished with smem
        // stage regs -> smem
#pragma unroll
        for (int i = 0; i < 3; i++) {
            int idx = t + i * 192;
            if (idx < 512) {
                int vl = idx & 127, q = idx >> 7;
                wsm[q * 4 + 0][vl] = wst[i].x;
                wsm[q * 4 + 1][vl] = wst[i].y;
                wsm[q * 4 + 2][vl] = wst[i].z;
                wsm[q * 4 + 3][vl] = wst[i].w;
            }
        }
#pragma unroll
        for (int i = 0; i < 2; i++) {
            int idx = t + i * 192;
            int r = idx % R_, q = idx / R_;
            hsm[q * 4 + 0][r] = make_float2(hst[i].x, hst[i].x);
            hsm[q * 4 + 1][r] = make_float2(hst[i].y, hst[i].y);
            hsm[q * 4 + 2][r] = make_float2(hst[i].z, hst[i].z);
            hsm[q * 4 + 3][r] = make_float2(hst[i].w, hst[i].w);
        }
        __syncthreads();                 // smem tile ready

        // prefetch next chunk (overlaps with compute below)
        if (c + 1 < NCHUNK) {
            const int k0 = (c + 1) * KB;
#pragma unroll
            for (int i = 0; i < 3; i++) {
                int idx = t + i * 192;
                if (idx < 512) {
                    int vl = idx & 127, q = idx >> 7;
                    int v = vbase + vl;
                    wst[i] = (v < V_) ? *reinterpret_cast<const float4*>(w + (size_t)v * D_ + k0 + q * 4)
                                      : make_float4(0.f, 0.f, 0.f, 0.f);
                }
            }
#pragma unroll
            for (int i = 0; i < 2; i++) {
                int idx = t + i * 192;
                int r = idx % R_, q = idx / R_;
                hst[i] = *reinterpret_cast<const float4*>(g_h + r * D_ + k0 + q * 4);
            }
        }

        // compute on smem chunk
#pragma unroll 8
        for (int kk = 0; kk < KB; kk++) {
            const ulonglong2* hp =
                reinterpret_cast<const ulonglong2*>(&hsm[kk][rt * 8]);
            ulonglong2 Ha = hp[0], Hb = hp[1], Hc = hp[2], Hd = hp[3];
            const ulonglong2* wp =
                reinterpret_cast<const ulonglong2*>(&wsm[kk][vt * 8]);
            ulonglong2 Wa = wp[0], Wb = wp[1];

            ull hh[8] = {Ha.x, Ha.y, Hb.x, Hb.y, Hc.x, Hc.y, Hd.x, Hd.y};
            ull ww[4] = {Wa.x, Wa.y, Wb.x, Wb.y};

#pragma unroll
            for (int i = 0; i < 8; i++)
#pragma unroll
                for (int j = 0; j < 4; j++)
                    FMA2(acc[i][j], hh[i], ww[j]);
        }
    }

    // ---- fused epilogue: mask, online softmax, argmax ----
    float m[8], s[8];
    int bi[8];
#pragma unroll
    for (int i = 0; i < 8; i++) { m[i] = -INFINITY; s[i] = 0.f; bi[i] = 0x7fffffff; }

#pragma unroll
    for (int i = 0; i < 8; i++) {
        int row = rt * 8 + i;
        int b = row & (B_ - 1);
        const unsigned int* pres = g_present + b * PW;
#pragma unroll
        for (int j = 0; j < 8; j++) {
            int v = vbase + vt * 8 + j;
            if (v < V_) {
                unsigned int wd = pres[v >> 5];
                if ((wd >> (v & 31)) & 1u) {
                    float2 p = unpack2(acc[i][j >> 1]);
                    float x = (j & 1) ? p.y : p.x;
                    sm_combine(m[i], s[i], bi[i], x, 1.0f, v);
                }
            }
        }
    }
#pragma unroll
    for (int off = 8; off; off >>= 1) {
#pragma unroll
        for (int i = 0; i < 8; i++) {
            float m2 = __shfl_down_sync(0xffffffffu, m[i], off, 16);
            float s2 = __shfl_down_sync(0xffffffffu, s[i], off, 16);
            int   b2 = __shfl_down_sync(0xffffffffu, bi[i], off, 16);
            sm_combine(m[i], s[i], bi[i], m2, s2, b2);
        }
    }
    if (vt == 0) {
#pragma unroll
        for (int i = 0; i < 8; i++) {
            int row = rt * 8 + i;
            g_pm[tile * R_ + row] = m[i];
            g_ps[tile * R_ + row] = s[i];
            g_pi[tile * R_ + row] = bi[i];
        }
    }
}

// Per-row reduction over tile partials + tgt logit dot product.
__global__ void reduce_rows_kernel(const float* __restrict__ w,
                                   const int* __restrict__ tgts,
                                   const int* __restrict__ astarts) {
    __shared__ float smm[128], sms[128], sdot[128];
    __shared__ int smi[128];
    const int r = blockIdx.x;           // r = l*16 + b
    const int t = threadIdx.x;
    const int b = r & (B_ - 1);
    const int l = r >> 4;

    float m = -INFINITY, s = 0.f;
    int bi = 0x7fffffff;
    for (int tile = t; tile < NT; tile += 128)
        sm_combine(m, s, bi, g_pm[tile * R_ + r], g_ps[tile * R_ + r], g_pi[tile * R_ + r]);
    smm[t] = m; sms[t] = s; smi[t] = bi;

    int tgt = tgts[b * L_ + l];
    int tc = (tgt >= 0 && tgt < V_) ? tgt : 0;
    float dot = 0.f;
    for (int d = t; d < D_; d += 128)
        dot += w[(size_t)tc * D_ + d] * g_h[r * D_ + d];
    sdot[t] = dot;
    __syncthreads();

    for (int off = 64; off; off >>= 1) {
        if (t < off) {
            sm_combine(smm[t], sms[t], smi[t], smm[t + off], sms[t + off], smi[t + off]);
            sdot[t] += sdot[t + off];
        }
        __syncthreads();
    }

    if (t == 0) {
        float lse = smm[0] + logf(sms[0]);
        float nll = lse - sdot[0];
        int as = astarts[b];
        bool in_range = (as >= 1) && (as < T_);
        bool ptgt = (tgt >= 0 && tgt < V_) &&
                    ((g_present[b * PW + (tgt >> 5)] >> (tgt & 31)) & 1u);
        bool valid = ptgt && in_range;
        int pred = smi[0];
        g_rownll[r]   = valid ? nll : 0.f;
        g_rowacc[r]   = (valid && pred == tgt) ? 1.f : 0.f;
        g_rowvalid[r] = valid ? 1 : 0;
    }
}

__global__ void finalize_kernel(float* __restrict__ out) {
    if (threadIdx.x == 0) {
        float avg_loss = 0.f, avg_acc = 0.f, final_acc = 0.f;
        int nhas = 0;
        for (int l = 0; l < L_; l++) {
            float cnt = 0.f, sl = 0.f, sa = 0.f;
            for (int b = 0; b < B_; b++) {
                int r = l * B_ + b;
                cnt += (float)g_rowvalid[r];
                sl  += g_rownll[r];
                sa  += g_rowacc[r];
            }
            float denom = fmaxf(cnt, 1.f);
            float ll = sl / denom;
            float la = sa / denom;
            if (cnt > 0.f) { nhas++; avg_loss += ll; avg_acc += la; }
            if (l == L_ - 1) final_acc = la;
        }
        float nv = fmaxf((float)nhas, 1.f);
        out[0] = avg_loss / nv;
        out[1] = avg_acc / nv;
        out[2] = final_acc;
    }
}

extern "C" void kernel_launch(void* const* d_in, const int* in_sizes, int n_in,
                              void* d_out, int out_size) {
    const float* x = nullptr;
    const float* w = nullptr;
    const int* ids = nullptr;
    const int* tgts = nullptr;
    const int* astarts = nullptr;
    for (int i = 0; i < n_in; i++) {
        long sz = (long)in_sizes[i];
        if (sz == (long)L_ * B_ * T_ * D_)      x = (const float*)d_in[i];
        else if (sz == (long)V_ * D_)           w = (const float*)d_in[i];
        else if (sz == (long)B_ * T_)           ids = (const int*)d_in[i];
        else if (sz == (long)B_ * L_)           tgts = (const int*)d_in[i];
        else if (sz == (long)B_)                astarts = (const int*)d_in[i];
    }

    zero_present_kernel<<<(B_ * PW + 255) / 256, 256>>>();
    scatter_kernel<<<(B_ * T_ + 255) / 256, 256>>>(ids);
    gather_kernel<<<R_, 256>>>(x, astarts);
    gemm_kernel<<<NT, 192>>>(w);
    reduce_rows_kernel<<<R_, 128>>>(w, tgts, astarts);
    finalize_kernel<<<1, 32>>>((float*)d_out);
}

// round 6
// speedup vs baseline: 2.7831x; 2.7831x over previous
#include <cuda_runtime.h>
#include <cuda_bf16.h>
#include <math.h>
#include <stdint.h>

// Problem constants
#define L_  6
#define B_  16
#define T_  2048
#define D_  768
#define V_  50280
#define R_  96               // L_*B_ rows
#define PW  1572             // ceil(V_/32) bitmap words per batch row

// GEMM tiling (mma.sync m16n8k16 bf16, hi/lo split)
#define NTILE 128            // vocab per CTA
#define NT    393            // ceil(V_/128)
#define KC    32             // K chunk
#define NCH   (D_ / KC)      // 24

// Padded smem rows: 56 bf16 = 112 B (16B-aligned, conflict-free ldmatrix)
#define RSTRIDE   112
#define OFF_AHI   0
#define OFF_ALO   (96 * RSTRIDE)                 // 10752
#define OFF_BHI   (2 * 96 * RSTRIDE)             // 21504
#define OFF_BLO   (2 * 96 * RSTRIDE + 128 * RSTRIDE)   // 35840
#define STAGE_SZ  (2 * 96 * RSTRIDE + 2 * 128 * RSTRIDE) // 50176
#define DYN_SZ    (2 * STAGE_SZ)                 // 100352

typedef unsigned long long ull;

// -------- device scratch --------
__device__ unsigned int g_present[B_ * PW];
__device__ float g_h[R_ * D_];
__device__ __nv_bfloat16 g_h_hi[R_ * D_];
__device__ __nv_bfloat16 g_h_lo[R_ * D_];
__device__ float g_pm[NT * R_];
__device__ float g_ps[NT * R_];
__device__ int   g_pi[NT * R_];
__device__ float g_rownll[R_];
__device__ float g_rowacc[R_];
__device__ int   g_rowvalid[R_];

// -------- helpers --------
__device__ __forceinline__ uint32_t smem_u32(const void* p) {
    uint32_t a;
    asm("{ .reg .u64 t; cvta.to.shared.u64 t, %1; cvt.u32.u64 %0, t; }" : "=r"(a) : "l"(p));
    return a;
}

#define LDMATRIX_X4(r0, r1, r2, r3, addr) \
    asm volatile("ldmatrix.sync.aligned.m8n8.x4.shared.b16 {%0,%1,%2,%3}, [%4];" \
                 : "=r"(r0), "=r"(r1), "=r"(r2), "=r"(r3) : "r"(addr))

#define MMA16816(c0, c1, c2, c3, a0, a1, a2, a3, b0, b1) \
    asm volatile("mma.sync.aligned.m16n8k16.row.col.f32.bf16.bf16.f32 " \
                 "{%0,%1,%2,%3}, {%4,%5,%6,%7}, {%8,%9}, {%0,%1,%2,%3};" \
                 : "+f"(c0), "+f"(c1), "+f"(c2), "+f"(c3) \
                 : "r"(a0), "r"(a1), "r"(a2), "r"(a3), "r"(b0), "r"(b1))

__device__ __forceinline__ void sm_combine(float& m, float& s, int& bi,
                                           float m2, float s2, int bi2) {
    if (m2 > m) {
        s = s * __expf(m - m2) + s2;
        m = m2;
        bi = bi2;
    } else if (m2 == m) {
        s += s2;
        if (bi2 < bi) bi = bi2;
    } else {
        s += s2 * __expf(m2 - m);
    }
}

__device__ __forceinline__ void split_pair(float a, float b, unsigned& hi, unsigned& lo) {
    __nv_bfloat16 ah = __float2bfloat16_rn(a);
    __nv_bfloat16 bh = __float2bfloat16_rn(b);
    float ar = a - __bfloat162float(ah);
    float br = b - __bfloat162float(bh);
    __nv_bfloat16 al = __float2bfloat16_rn(ar);
    __nv_bfloat16 bl = __float2bfloat16_rn(br);
    hi = ((unsigned)__bfloat16_as_ushort(bh) << 16) | __bfloat16_as_ushort(ah);
    lo = ((unsigned)__bfloat16_as_ushort(bl) << 16) | __bfloat16_as_ushort(al);
}

// -------- small kernels --------
__global__ void zero_present_kernel() {
    int i = blockIdx.x * blockDim.x + threadIdx.x;
    if (i < B_ * PW) g_present[i] = 0u;
}

__global__ void scatter_kernel(const int* __restrict__ ids) {
    int i = blockIdx.x * blockDim.x + threadIdx.x;
    if (i < B_ * T_) {
        int b = i / T_;
        int tok = ids[i];
        if (tok >= 0 && tok < V_)
            atomicOr(&g_present[b * PW + (tok >> 5)], 1u << (tok & 31));
    }
}

__global__ void gather_kernel(const float* __restrict__ x,
                              const int* __restrict__ astarts) {
    int r = blockIdx.x;                 // 0..95
    int b = r & (B_ - 1);
    int tt = astarts[b] - 1;
    if (tt < 0) tt = 0;
    if (tt >= T_) tt = T_ - 1;
    const float* src = x + ((size_t)r * T_ + (size_t)tt) * D_;
    for (int d = threadIdx.x; d < D_; d += blockDim.x) {
        float f = src[d];
        g_h[r * D_ + d] = f;
        __nv_bfloat16 h = __float2bfloat16_rn(f);
        float lo = f - __bfloat162float(h);
        g_h_hi[r * D_ + d] = h;
        g_h_lo[r * D_ + d] = __float2bfloat16_rn(lo);
    }
}

// ---------------- HMMA GEMM ----------------
// 96 rows x 128 vocab per CTA, K=768. acc = Ahi*Bhi + Ahi*Blo + Alo*Bhi (fp32 acc).
// 8 warps = 2 (M, 48 rows) x 4 (N, 32 cols). mma.sync m16n8k16 bf16.
__global__ void __launch_bounds__(256, 2) gemm_tc(const float* __restrict__ w) {
    extern __shared__ __align__(16) char dynsmem[];
    const uint32_t base_u = smem_u32(dynsmem);

    const int t = threadIdx.x;
    const int wid = t >> 5, lane = t & 31;
    const int warp_m = wid >> 2;        // 0..1
    const int warp_n = wid & 3;         // 0..3
    const int g  = lane >> 2;           // 0..7
    const int tq = lane & 3;            // 0..3
    const int tile = blockIdx.x;
    const int vbase = tile * NTILE;

    // ldmatrix lane-address components
    const int ti = lane >> 3;                       // 0..3
    const int a_row  = (lane & 7) + ((ti & 1) << 3);   // A: rows interleaved lo/hi
    const int a_koff = (ti >> 1) << 4;                 // +16B for k>=8
    const int b_col  = (lane & 7) + ((ti >> 1) << 3);  // B: cols 0..7 then 8..15
    const int b_koff = (ti & 1) << 4;

    float acc[3][4][4];
#pragma unroll
    for (int i = 0; i < 3; i++)
#pragma unroll
        for (int j = 0; j < 4; j++)
#pragma unroll
            for (int k = 0; k < 4; k++) acc[i][j][k] = 0.f;

    // ---- stage chunk 0 directly ----
    {
        char* stg = dynsmem;
        const int k0 = 0;
#pragma unroll
        for (int i = 0; i < 4; i++) {
            int idx = t + i * 256;      // 0..1023
            int n = idx >> 3, q = idx & 7;
            int v = vbase + n;
            float4 val = make_float4(0.f, 0.f, 0.f, 0.f);
            if (v < V_)
                val = *reinterpret_cast<const float4*>(w + (size_t)v * D_ + k0 + q * 4);
            unsigned h01, l01, h23, l23;
            split_pair(val.x, val.y, h01, l01);
            split_pair(val.z, val.w, h23, l23);
            *reinterpret_cast<uint2*>(stg + OFF_BHI + n * RSTRIDE + q * 8) = make_uint2(h01, h23);
            *reinterpret_cast<uint2*>(stg + OFF_BLO + n * RSTRIDE + q * 8) = make_uint2(l01, l23);
        }
#pragma unroll
        for (int i = 0; i < 3; i++) {
            int idx = t + i * 256;      // 0..767
            int row = idx >> 3, q = idx & 7;
            uint2 hv = *reinterpret_cast<const uint2*>(g_h_hi + row * D_ + k0 + q * 4);
            uint2 lv = *reinterpret_cast<const uint2*>(g_h_lo + row * D_ + k0 + q * 4);
            *reinterpret_cast<uint2*>(stg + OFF_AHI + row * RSTRIDE + q * 8) = hv;
            *reinterpret_cast<uint2*>(stg + OFF_ALO + row * RSTRIDE + q * 8) = lv;
        }
    }
    __syncthreads();

    for (int c = 0; c < NCH; c++) {
        const int s = c & 1;
        const uint32_t stg_u = base_u + s * STAGE_SZ;

        // prefetch next chunk into registers (overlaps HMMA below)
        float4 wreg[4];
        uint2 ahreg[3], alreg[3];
        const bool more = (c + 1 < NCH);
        if (more) {
            const int k0 = (c + 1) * KC;
#pragma unroll
            for (int i = 0; i < 4; i++) {
                int idx = t + i * 256;
                int n = idx >> 3, q = idx & 7;
                int v = vbase + n;
                wreg[i] = (v < V_)
                    ? *reinterpret_cast<const float4*>(w + (size_t)v * D_ + k0 + q * 4)
                    : make_float4(0.f, 0.f, 0.f, 0.f);
            }
#pragma unroll
            for (int i = 0; i < 3; i++) {
                int idx = t + i * 256;
                int row = idx >> 3, q = idx & 7;
                ahreg[i] = *reinterpret_cast<const uint2*>(g_h_hi + row * D_ + k0 + q * 4);
                alreg[i] = *reinterpret_cast<const uint2*>(g_h_lo + row * D_ + k0 + q * 4);
            }
        }

        // ---- compute on chunk c ----
#pragma unroll
        for (int ks = 0; ks < 2; ks++) {
            const uint32_t kbyte = ks * 32;
            // B fragments: 2 x4-ldmatrix per half (16 cols each)
            uint32_t bh[8], bl[8];
#pragma unroll
            for (int p = 0; p < 2; p++) {
                uint32_t baddr = stg_u + OFF_BHI +
                    (uint32_t)(warp_n * 32 + p * 16 + b_col) * RSTRIDE + kbyte + b_koff;
                LDMATRIX_X4(bh[p * 4 + 0], bh[p * 4 + 1], bh[p * 4 + 2], bh[p * 4 + 3], baddr);
                uint32_t laddr = baddr + (OFF_BLO - OFF_BHI);
                LDMATRIX_X4(bl[p * 4 + 0], bl[p * 4 + 1], bl[p * 4 + 2], bl[p * 4 + 3], laddr);
            }
#pragma unroll
            for (int mf = 0; mf < 3; mf++) {
                uint32_t aaddr = stg_u + OFF_AHI +
                    (uint32_t)(warp_m * 48 + mf * 16 + a_row) * RSTRIDE + kbyte + a_koff;
                uint32_t ah0, ah1, ah2, ah3, al0, al1, al2, al3;
                LDMATRIX_X4(ah0, ah1, ah2, ah3, aaddr);
                LDMATRIX_X4(al0, al1, al2, al3, aaddr + (OFF_ALO - OFF_AHI));
#pragma unroll
                for (int nf = 0; nf < 4; nf++) {
                    uint32_t b0h = bh[(nf >> 1) * 4 + (nf & 1) * 2 + 0];
                    uint32_t b1h = bh[(nf >> 1) * 4 + (nf & 1) * 2 + 1];
                    uint32_t b0l = bl[(nf >> 1) * 4 + (nf & 1) * 2 + 0];
                    uint32_t b1l = bl[(nf >> 1) * 4 + (nf & 1) * 2 + 1];
                    float* a4 = acc[mf][nf];
                    MMA16816(a4[0], a4[1], a4[2], a4[3], ah0, ah1, ah2, ah3, b0h, b1h);
                    MMA16816(a4[0], a4[1], a4[2], a4[3], ah0, ah1, ah2, ah3, b0l, b1l);
                    MMA16816(a4[0], a4[1], a4[2], a4[3], al0, al1, al2, al3, b0h, b1h);
                }
            }
        }

        // ---- store prefetched regs into the other stage ----
        if (more) {
            char* stg2 = dynsmem + (s ^ 1) * STAGE_SZ;
#pragma unroll
            for (int i = 0; i < 4; i++) {
                int idx = t + i * 256;
                int n = idx >> 3, q = idx & 7;
                unsigned h01, l01, h23, l23;
                split_pair(wreg[i].x, wreg[i].y, h01, l01);
                split_pair(wreg[i].z, wreg[i].w, h23, l23);
                *reinterpret_cast<uint2*>(stg2 + OFF_BHI + n * RSTRIDE + q * 8) = make_uint2(h01, h23);
                *reinterpret_cast<uint2*>(stg2 + OFF_BLO + n * RSTRIDE + q * 8) = make_uint2(l01, l23);
            }
#pragma unroll
            for (int i = 0; i < 3; i++) {
                int idx = t + i * 256;
                int row = idx >> 3, q = idx & 7;
                *reinterpret_cast<uint2*>(stg2 + OFF_AHI + row * RSTRIDE + q * 8) = ahreg[i];
                *reinterpret_cast<uint2*>(stg2 + OFF_ALO + row * RSTRIDE + q * 8) = alreg[i];
            }
        }
        __syncthreads();
    }

    // ---- epilogue: park logits in smem (row stride 129 floats) ----
    float* lg = reinterpret_cast<float*>(dynsmem);
#pragma unroll
    for (int mf = 0; mf < 3; mf++) {
        int row0 = warp_m * 48 + mf * 16 + g;
#pragma unroll
        for (int nf = 0; nf < 4; nf++) {
            int col = warp_n * 32 + nf * 8 + tq * 2;
            lg[row0 * 129 + col]           = acc[mf][nf][0];
            lg[row0 * 129 + col + 1]       = acc[mf][nf][1];
            lg[(row0 + 8) * 129 + col]     = acc[mf][nf][2];
            lg[(row0 + 8) * 129 + col + 1] = acc[mf][nf][3];
        }
    }
    __syncthreads();

    // ---- masked online softmax + argmax, one thread per row ----
    if (t < R_) {
        int b = t & (B_ - 1);
        const unsigned int* pres = g_present + b * PW;
        const float* lrow = lg + t * 129;
        float mm = -INFINITY, ss = 0.f;
        int bi = 0x7fffffff;
#pragma unroll
        for (int cw = 0; cw < 4; cw++) {
            unsigned wd = pres[(vbase >> 5) + cw];
            if (wd) {
#pragma unroll 4
                for (int j = 0; j < 32; j++) {
                    if ((wd >> j) & 1u) {
                        int cc = cw * 32 + j;
                        sm_combine(mm, ss, bi, lrow[cc], 1.0f, vbase + cc);
                    }
                }
            }
        }
        g_pm[tile * R_ + t] = mm;
        g_ps[tile * R_ + t] = ss;
        g_pi[tile * R_ + t] = bi;
    }
}

// Per-row reduction over tile partials + tgt logit dot product.
__global__ void reduce_rows_kernel(const float* __restrict__ w,
                                   const int* __restrict__ tgts,
                                   const int* __restrict__ astarts) {
    __shared__ float smm[128], sms[128], sdot[128];
    __shared__ int smi[128];
    const int r = blockIdx.x;           // r = l*16 + b
    const int t = threadIdx.x;
    const int b = r & (B_ - 1);
    const int l = r >> 4;

    float m = -INFINITY, s = 0.f;
    int bi = 0x7fffffff;
    for (int tile = t; tile < NT; tile += 128)
        sm_combine(m, s, bi, g_pm[tile * R_ + r], g_ps[tile * R_ + r], g_pi[tile * R_ + r]);
    smm[t] = m; sms[t] = s; smi[t] = bi;

    int tgt = tgts[b * L_ + l];
    int tc = (tgt >= 0 && tgt < V_) ? tgt : 0;
    float dot = 0.f;
    for (int d = t; d < D_; d += 128)
        dot += w[(size_t)tc * D_ + d] * g_h[r * D_ + d];
    sdot[t] = dot;
    __syncthreads();

    for (int off = 64; off; off >>= 1) {
        if (t < off) {
            sm_combine(smm[t], sms[t], smi[t], smm[t + off], sms[t + off], smi[t + off]);
            sdot[t] += sdot[t + off];
        }
        __syncthreads();
    }

    if (t == 0) {
        float lse = smm[0] + logf(sms[0]);
        float nll = lse - sdot[0];
        int as = astarts[b];
        bool in_range = (as >= 1) && (as < T_);
        bool ptgt = (tgt >= 0 && tgt < V_) &&
                    ((g_present[b * PW + (tgt >> 5)] >> (tgt & 31)) & 1u);
        bool valid = ptgt && in_range;
        int pred = smi[0];
        g_rownll[r]   = valid ? nll : 0.f;
        g_rowacc[r]   = (valid && pred == tgt) ? 1.f : 0.f;
        g_rowvalid[r] = valid ? 1 : 0;
    }
}

__global__ void finalize_kernel(float* __restrict__ out) {
    if (threadIdx.x == 0) {
        float avg_loss = 0.f, avg_acc = 0.f, final_acc = 0.f;
        int nhas = 0;
        for (int l = 0; l < L_; l++) {
            float cnt = 0.f, sl = 0.f, sa = 0.f;
            for (int b = 0; b < B_; b++) {
                int r = l * B_ + b;
                cnt += (float)g_rowvalid[r];
                sl  += g_rownll[r];
                sa  += g_rowacc[r];
            }
            float denom = fmaxf(cnt, 1.f);
            float ll = sl / denom;
            float la = sa / denom;
            if (cnt > 0.f) { nhas++; avg_loss += ll; avg_acc += la; }
            if (l == L_ - 1) final_acc = la;
        }
        float nv = fmaxf((float)nhas, 1.f);
        out[0] = avg_loss / nv;
        out[1] = avg_acc / nv;
        out[2] = final_acc;
    }
}

extern "C" void kernel_launch(void* const* d_in, const int* in_sizes, int n_in,
                              void* d_out, int out_size) {
    const float* x = nullptr;
    const float* w = nullptr;
    const int* ids = nullptr;
    const int* tgts = nullptr;
    const int* astarts = nullptr;
    for (int i = 0; i < n_in; i++) {
        long sz = (long)in_sizes[i];
        if (sz == (long)L_ * B_ * T_ * D_)      x = (const float*)d_in[i];
        else if (sz == (long)V_ * D_)           w = (const float*)d_in[i];
        else if (sz == (long)B_ * T_)           ids = (const int*)d_in[i];
        else if (sz == (long)B_ * L_)           tgts = (const int*)d_in[i];
        else if (sz == (long)B_)                astarts = (const int*)d_in[i];
    }

    static int attr_set = 0;
    if (!attr_set) {
        cudaFuncSetAttribute(gemm_tc, cudaFuncAttributeMaxDynamicSharedMemorySize, DYN_SZ);
        attr_set = 1;
    }

    zero_present_kernel<<<(B_ * PW + 255) / 256, 256>>>();
    scatter_kernel<<<(B_ * T_ + 255) / 256, 256>>>(ids);
    gather_kernel<<<R_, 256>>>(x, astarts);
    gemm_tc<<<NT, 256, DYN_SZ>>>(w);
    reduce_rows_kernel<<<R_, 128>>>(w, tgts, astarts);
    finalize_kernel<<<1, 32>>>((float*)d_out);
}

// round 7
// speedup vs baseline: 2.8130x; 1.0107x over previous
#include <cuda_runtime.h>
#include <cuda_bf16.h>
#include <math.h>
#include <stdint.h>

// Problem constants
#define L_  6
#define B_  16
#define T_  2048
#define D_  768
#define V_  50280
#define R_  96               // L_*B_ rows
#define PW  1572             // ceil(V_/32) bitmap words per batch row

// GEMM tiling (mma.sync m16n8k16 bf16, hi/lo split)
#define NTILE 128            // vocab per CTA tile
#define NT    393            // ceil(V_/128)
#define KC    32             // K chunk
#define NCH   (D_ / KC)      // 24
#define GRID_P 296           // persistent grid: 148 SMs x 2 CTAs

// Padded smem rows: 56 bf16 = 112 B (16B-aligned, conflict-free ldmatrix)
#define RSTRIDE   112
#define OFF_AHI   0
#define OFF_ALO   (96 * RSTRIDE)                 // 10752
#define OFF_BHI   (2 * 96 * RSTRIDE)             // 21504
#define OFF_BLO   (2 * 96 * RSTRIDE + 128 * RSTRIDE)   // 35840
#define STAGE_SZ  (2 * 96 * RSTRIDE + 2 * 128 * RSTRIDE) // 50176
#define DYN_SZ    (2 * STAGE_SZ)                 // 100352

typedef unsigned long long ull;

// -------- device scratch --------
__device__ unsigned int g_present[B_ * PW];
__device__ float g_h[R_ * D_];
__device__ __nv_bfloat16 g_h_hi[R_ * D_];
__device__ __nv_bfloat16 g_h_lo[R_ * D_];
__device__ float g_pm[NT * R_];
__device__ float g_ps[NT * R_];
__device__ int   g_pi[NT * R_];
__device__ float g_rownll[R_];
__device__ float g_rowacc[R_];
__device__ int   g_rowvalid[R_];

// -------- helpers --------
__device__ __forceinline__ uint32_t smem_u32(const void* p) {
    uint32_t a;
    asm("{ .reg .u64 t; cvta.to.shared.u64 t, %1; cvt.u32.u64 %0, t; }" : "=r"(a) : "l"(p));
    return a;
}

#define LDMATRIX_X4(r0, r1, r2, r3, addr) \
    asm volatile("ldmatrix.sync.aligned.m8n8.x4.shared.b16 {%0,%1,%2,%3}, [%4];" \
                 : "=r"(r0), "=r"(r1), "=r"(r2), "=r"(r3) : "r"(addr))

#define MMA16816(c0, c1, c2, c3, a0, a1, a2, a3, b0, b1) \
    asm volatile("mma.sync.aligned.m16n8k16.row.col.f32.bf16.bf16.f32 " \
                 "{%0,%1,%2,%3}, {%4,%5,%6,%7}, {%8,%9}, {%0,%1,%2,%3};" \
                 : "+f"(c0), "+f"(c1), "+f"(c2), "+f"(c3) \
                 : "r"(a0), "r"(a1), "r"(a2), "r"(a3), "r"(b0), "r"(b1))

#define CP_ASYNC16(dst_u32, src_ptr) \
    asm volatile("cp.async.ca.shared.global [%0], [%1], 16;" \
                 :: "r"(dst_u32), "l"(src_ptr) : "memory")
#define CP_COMMIT() asm volatile("cp.async.commit_group;" ::: "memory")
#define CP_WAIT0()  asm volatile("cp.async.wait_group 0;" ::: "memory")

__device__ __forceinline__ void sm_combine(float& m, float& s, int& bi,
                                           float m2, float s2, int bi2) {
    if (m2 > m) {
        s = s * __expf(m - m2) + s2;
        m = m2;
        bi = bi2;
    } else if (m2 == m) {
        s += s2;
        if (bi2 < bi) bi = bi2;
    } else {
        s += s2 * __expf(m2 - m);
    }
}

__device__ __forceinline__ void split_pair(float a, float b, unsigned& hi, unsigned& lo) {
    __nv_bfloat16 ah = __float2bfloat16_rn(a);
    __nv_bfloat16 bh = __float2bfloat16_rn(b);
    float ar = a - __bfloat162float(ah);
    float br = b - __bfloat162float(bh);
    __nv_bfloat16 al = __float2bfloat16_rn(ar);
    __nv_bfloat16 bl = __float2bfloat16_rn(br);
    hi = ((unsigned)__bfloat16_as_ushort(bh) << 16) | __bfloat16_as_ushort(ah);
    lo = ((unsigned)__bfloat16_as_ushort(bl) << 16) | __bfloat16_as_ushort(al);
}

// -------- small kernels --------
__global__ void zero_present_kernel() {
    int i = blockIdx.x * blockDim.x + threadIdx.x;
    if (i < B_ * PW) g_present[i] = 0u;
}

__global__ void scatter_kernel(const int* __restrict__ ids) {
    int i = blockIdx.x * blockDim.x + threadIdx.x;
    if (i < B_ * T_) {
        int b = i / T_;
        int tok = ids[i];
        if (tok >= 0 && tok < V_)
            atomicOr(&g_present[b * PW + (tok >> 5)], 1u << (tok & 31));
    }
}

__global__ void gather_kernel(const float* __restrict__ x,
                              const int* __restrict__ astarts) {
    int r = blockIdx.x;                 // 0..95
    int b = r & (B_ - 1);
    int tt = astarts[b] - 1;
    if (tt < 0) tt = 0;
    if (tt >= T_) tt = T_ - 1;
    const float* src = x + ((size_t)r * T_ + (size_t)tt) * D_;
    for (int d = threadIdx.x; d < D_; d += blockDim.x) {
        float f = src[d];
        g_h[r * D_ + d] = f;
        __nv_bfloat16 h = __float2bfloat16_rn(f);
        float lo = f - __bfloat162float(h);
        g_h_hi[r * D_ + d] = h;
        g_h_lo[r * D_ + d] = __float2bfloat16_rn(lo);
    }
}

// ---------------- HMMA GEMM (persistent) ----------------
// Per tile: 96 rows x 128 vocab, K=768; acc = Ahi*Bhi + Ahi*Blo + Alo*Bhi.
// 8 warps = 2 (M, 48 rows) x 4 (N, 32 cols). A chunks via cp.async (bf16 in
// gmem already); W fp32 via register-staged LDG + in-flight hi/lo split.
__global__ void __launch_bounds__(256, 2) gemm_tc(const float* __restrict__ w) {
    extern __shared__ __align__(16) char dynsmem[];
    const uint32_t base_u = smem_u32(dynsmem);

    const int t = threadIdx.x;
    const int wid = t >> 5, lane = t & 31;
    const int warp_m = wid >> 2;        // 0..1
    const int warp_n = wid & 3;         // 0..3
    const int g  = lane >> 2;           // 0..7
    const int tq = lane & 3;            // 0..3

    // ldmatrix lane-address components
    const int ti = lane >> 3;                          // 0..3
    const int a_row  = (lane & 7) + ((ti & 1) << 3);
    const int a_koff = (ti >> 1) << 4;
    const int b_col  = (lane & 7) + ((ti >> 1) << 3);
    const int b_koff = (ti & 1) << 4;

    // A cp.async decomposition: idx 0..767 -> half(hi/lo), row, 16B unit
    // per half: 96 rows x 4 units

    for (int tile = blockIdx.x; tile < NT; tile += gridDim.x) {
        const int vbase = tile * NTILE;

        float acc[3][4][4];
#pragma unroll
        for (int i = 0; i < 3; i++)
#pragma unroll
            for (int j = 0; j < 4; j++)
#pragma unroll
                for (int k = 0; k < 4; k++) acc[i][j][k] = 0.f;

        // ---- prologue: stage chunk 0 ----
        {
            char* stg = dynsmem;
            const int k0 = 0;
            // A via cp.async
#pragma unroll
            for (int i = 0; i < 3; i++) {
                int idx = t + i * 256;          // 0..767
                int half = idx >= 384;
                int j = idx - half * 384;
                int row = j >> 2, q = j & 3;
                const __nv_bfloat16* src =
                    (half ? g_h_lo : g_h_hi) + row * D_ + k0 + q * 8;
                uint32_t dst = base_u + (half ? OFF_ALO : OFF_AHI) +
                               (uint32_t)(row * RSTRIDE + q * 16);
                CP_ASYNC16(dst, src);
            }
            CP_COMMIT();
            // W: LDG fp32 -> split -> STS
#pragma unroll
            for (int i = 0; i < 4; i++) {
                int idx = t + i * 256;          // 0..1023
                int n = idx >> 3, q = idx & 7;
                int v = vbase + n;
                float4 val = (v < V_)
                    ? *reinterpret_cast<const float4*>(w + (size_t)v * D_ + k0 + q * 4)
                    : make_float4(0.f, 0.f, 0.f, 0.f);
                unsigned h01, l01, h23, l23;
                split_pair(val.x, val.y, h01, l01);
                split_pair(val.z, val.w, h23, l23);
                *reinterpret_cast<uint2*>(stg + OFF_BHI + n * RSTRIDE + q * 8) = make_uint2(h01, h23);
                *reinterpret_cast<uint2*>(stg + OFF_BLO + n * RSTRIDE + q * 8) = make_uint2(l01, l23);
            }
            CP_WAIT0();
        }
        __syncthreads();

        for (int c = 0; c < NCH; c++) {
            const int s = c & 1;
            const uint32_t stg_u = base_u + s * STAGE_SZ;
            const bool more = (c + 1 < NCH);

            // ---- issue next chunk's A cp.async + W LDG early ----
            float4 wreg[4];
            if (more) {
                const int k0 = (c + 1) * KC;
                const uint32_t st2 = base_u + (s ^ 1) * STAGE_SZ;
#pragma unroll
                for (int i = 0; i < 3; i++) {
                    int idx = t + i * 256;
                    int half = idx >= 384;
                    int j = idx - half * 384;
                    int row = j >> 2, q = j & 3;
                    const __nv_bfloat16* src =
                        (half ? g_h_lo : g_h_hi) + row * D_ + k0 + q * 8;
                    uint32_t dst = st2 + (half ? OFF_ALO : OFF_AHI) +
                                   (uint32_t)(row * RSTRIDE + q * 16);
                    CP_ASYNC16(dst, src);
                }
                CP_COMMIT();
#pragma unroll
                for (int i = 0; i < 4; i++) {
                    int idx = t + i * 256;
                    int n = idx >> 3, q = idx & 7;
                    int v = vbase + n;
                    wreg[i] = (v < V_)
                        ? *reinterpret_cast<const float4*>(w + (size_t)v * D_ + k0 + q * 4)
                        : make_float4(0.f, 0.f, 0.f, 0.f);
                }
            }

            // ---- compute on chunk c ----
#pragma unroll
            for (int ks = 0; ks < 2; ks++) {
                const uint32_t kbyte = ks * 32;
                uint32_t bh[8], bl[8];
#pragma unroll
                for (int p = 0; p < 2; p++) {
                    uint32_t baddr = stg_u + OFF_BHI +
                        (uint32_t)(warp_n * 32 + p * 16 + b_col) * RSTRIDE + kbyte + b_koff;
                    LDMATRIX_X4(bh[p * 4 + 0], bh[p * 4 + 1], bh[p * 4 + 2], bh[p * 4 + 3], baddr);
                    LDMATRIX_X4(bl[p * 4 + 0], bl[p * 4 + 1], bl[p * 4 + 2], bl[p * 4 + 3],
                                baddr + (OFF_BLO - OFF_BHI));
                }
#pragma unroll
                for (int mf = 0; mf < 3; mf++) {
                    uint32_t aaddr = stg_u + OFF_AHI +
                        (uint32_t)(warp_m * 48 + mf * 16 + a_row) * RSTRIDE + kbyte + a_koff;
                    uint32_t ah0, ah1, ah2, ah3, al0, al1, al2, al3;
                    LDMATRIX_X4(ah0, ah1, ah2, ah3, aaddr);
                    LDMATRIX_X4(al0, al1, al2, al3, aaddr + (OFF_ALO - OFF_AHI));
#pragma unroll
                    for (int nf = 0; nf < 4; nf++) {
                        uint32_t b0h = bh[(nf >> 1) * 4 + (nf & 1) * 2 + 0];
                        uint32_t b1h = bh[(nf >> 1) * 4 + (nf & 1) * 2 + 1];
                        uint32_t b0l = bl[(nf >> 1) * 4 + (nf & 1) * 2 + 0];
                        uint32_t b1l = bl[(nf >> 1) * 4 + (nf & 1) * 2 + 1];
                        float* a4 = acc[mf][nf];
                        MMA16816(a4[0], a4[1], a4[2], a4[3], ah0, ah1, ah2, ah3, b0h, b1h);
                        MMA16816(a4[0], a4[1], a4[2], a4[3], ah0, ah1, ah2, ah3, b0l, b1l);
                        MMA16816(a4[0], a4[1], a4[2], a4[3], al0, al1, al2, al3, b0h, b1h);
                    }
                }
            }

            // ---- drain stage: W split -> STS, wait A cp.async ----
            if (more) {
                char* stg2 = dynsmem + (s ^ 1) * STAGE_SZ;
#pragma unroll
                for (int i = 0; i < 4; i++) {
                    int idx = t + i * 256;
                    int n = idx >> 3, q = idx & 7;
                    unsigned h01, l01, h23, l23;
                    split_pair(wreg[i].x, wreg[i].y, h01, l01);
                    split_pair(wreg[i].z, wreg[i].w, h23, l23);
                    *reinterpret_cast<uint2*>(stg2 + OFF_BHI + n * RSTRIDE + q * 8) = make_uint2(h01, h23);
                    *reinterpret_cast<uint2*>(stg2 + OFF_BLO + n * RSTRIDE + q * 8) = make_uint2(l01, l23);
                }
                CP_WAIT0();
            }
            __syncthreads();
        }

        // ---- epilogue: park logits in smem (row stride 129 floats) ----
        float* lg = reinterpret_cast<float*>(dynsmem);
#pragma unroll
        for (int mf = 0; mf < 3; mf++) {
            int row0 = warp_m * 48 + mf * 16 + g;
#pragma unroll
            for (int nf = 0; nf < 4; nf++) {
                int col = warp_n * 32 + nf * 8 + tq * 2;
                lg[row0 * 129 + col]           = acc[mf][nf][0];
                lg[row0 * 129 + col + 1]       = acc[mf][nf][1];
                lg[(row0 + 8) * 129 + col]     = acc[mf][nf][2];
                lg[(row0 + 8) * 129 + col + 1] = acc[mf][nf][3];
            }
        }
        __syncthreads();

        // ---- masked online softmax + argmax, one thread per row ----
        if (t < R_) {
            int b = t & (B_ - 1);
            const unsigned int* pres = g_present + b * PW;
            const float* lrow = lg + t * 129;
            float mm = -INFINITY, ss = 0.f;
            int bi = 0x7fffffff;
#pragma unroll
            for (int cw = 0; cw < 4; cw++) {
                unsigned wd = pres[(vbase >> 5) + cw];
                if (wd) {
#pragma unroll 4
                    for (int j = 0; j < 32; j++) {
                        if ((wd >> j) & 1u) {
                            int cc = cw * 32 + j;
                            sm_combine(mm, ss, bi, lrow[cc], 1.0f, vbase + cc);
                        }
                    }
                }
            }
            g_pm[tile * R_ + t] = mm;
            g_ps[tile * R_ + t] = ss;
            g_pi[tile * R_ + t] = bi;
        }
        __syncthreads();               // lg region reused by next tile's staging
    }
}

// Per-row reduction over tile partials + tgt logit dot product.
__global__ void reduce_rows_kernel(const float* __restrict__ w,
                                   const int* __restrict__ tgts,
                                   const int* __restrict__ astarts) {
    __shared__ float smm[128], sms[128], sdot[128];
    __shared__ int smi[128];
    const int r = blockIdx.x;           // r = l*16 + b
    const int t = threadIdx.x;
    const int b = r & (B_ - 1);
    const int l = r >> 4;

    float m = -INFINITY, s = 0.f;
    int bi = 0x7fffffff;
    for (int tile = t; tile < NT; tile += 128)
        sm_combine(m, s, bi, g_pm[tile * R_ + r], g_ps[tile * R_ + r], g_pi[tile * R_ + r]);
    smm[t] = m; sms[t] = s; smi[t] = bi;

    int tgt = tgts[b * L_ + l];
    int tc = (tgt >= 0 && tgt < V_) ? tgt : 0;
    float dot = 0.f;
    for (int d = t; d < D_; d += 128)
        dot += w[(size_t)tc * D_ + d] * g_h[r * D_ + d];
    sdot[t] = dot;
    __syncthreads();

    for (int off = 64; off; off >>= 1) {
        if (t < off) {
            sm_combine(smm[t], sms[t], smi[t], smm[t + off], sms[t + off], smi[t + off]);
            sdot[t] += sdot[t + off];
        }
        __syncthreads();
    }

    if (t == 0) {
        float lse = smm[0] + logf(sms[0]);
        float nll = lse - sdot[0];
        int as = astarts[b];
        bool in_range = (as >= 1) && (as < T_);
        bool ptgt = (tgt >= 0 && tgt < V_) &&
                    ((g_present[b * PW + (tgt >> 5)] >> (tgt & 31)) & 1u);
        bool valid = ptgt && in_range;
        int pred = smi[0];
        g_rownll[r]   = valid ? nll : 0.f;
        g_rowacc[r]   = (valid && pred == tgt) ? 1.f : 0.f;
        g_rowvalid[r] = valid ? 1 : 0;
    }
}

__global__ void finalize_kernel(float* __restrict__ out) {
    if (threadIdx.x == 0) {
        float avg_loss = 0.f, avg_acc = 0.f, final_acc = 0.f;
        int nhas = 0;
        for (int l = 0; l < L_; l++) {
            float cnt = 0.f, sl = 0.f, sa = 0.f;
            for (int b = 0; b < B_; b++) {
                int r = l * B_ + b;
                cnt += (float)g_rowvalid[r];
                sl  += g_rownll[r];
                sa  += g_rowacc[r];
            }
            float denom = fmaxf(cnt, 1.f);
            float ll = sl / denom;
            float la = sa / denom;
            if (cnt > 0.f) { nhas++; avg_loss += ll; avg_acc += la; }
            if (l == L_ - 1) final_acc = la;
        }
        float nv = fmaxf((float)nhas, 1.f);
        out[0] = avg_loss / nv;
        out[1] = avg_acc / nv;
        out[2] = final_acc;
    }
}

extern "C" void kernel_launch(void* const* d_in, const int* in_sizes, int n_in,
                              void* d_out, int out_size) {
    const float* x = nullptr;
    const float* w = nullptr;
    const int* ids = nullptr;
    const int* tgts = nullptr;
    const int* astarts = nullptr;
    for (int i = 0; i < n_in; i++) {
        long sz = (long)in_sizes[i];
        if (sz == (long)L_ * B_ * T_ * D_)      x = (const float*)d_in[i];
        else if (sz == (long)V_ * D_)           w = (const float*)d_in[i];
        else if (sz == (long)B_ * T_)           ids = (const int*)d_in[i];
        else if (sz == (long)B_ * L_)           tgts = (const int*)d_in[i];
        else if (sz == (long)B_)                astarts = (const int*)d_in[i];
    }

    static int attr_set = 0;
    if (!attr_set) {
        cudaFuncSetAttribute(gemm_tc, cudaFuncAttributeMaxDynamicSharedMemorySize, DYN_SZ);
        attr_set = 1;
    }

    zero_present_kernel<<<(B_ * PW + 255) / 256, 256>>>();
    scatter_kernel<<<(B_ * T_ + 255) / 256, 256>>>(ids);
    gather_kernel<<<R_, 256>>>(x, astarts);
    gemm_tc<<<GRID_P, 256, DYN_SZ>>>(w);
    reduce_rows_kernel<<<R_, 128>>>(w, tgts, astarts);
    finalize_kernel<<<1, 32>>>((float*)d_out);
}

// round 8
// speedup vs baseline: 3.2888x; 1.1692x over previous
#include <cuda_runtime.h>
#include <cuda_bf16.h>
#include <math.h>
#include <stdint.h>

// Problem constants
#define L_  6
#define B_  16
#define T_  2048
#define D_  768
#define V_  50280
#define R_  96               // L_*B_ rows
#define PW  1572             // ceil(V_/32) bitmap words per batch row

// GEMM tiling (mma.sync m16n8k16 bf16, hi/lo split)
#define NTILE 128            // vocab per CTA tile
#define NT    393            // max tiles (full V) — partial arrays sized for this
#define KC    32             // K chunk
#define NCH   (D_ / KC)      // 24
#define GRID_P 296           // persistent grid: 148 SMs x 2 CTAs
#define MAXC  33024          // max compacted columns (<= B*T) + pad

// Padded smem rows: 56 bf16 = 112 B (16B-aligned, conflict-free ldmatrix)
#define RSTRIDE   112
#define OFF_AHI   0
#define OFF_ALO   (96 * RSTRIDE)
#define OFF_BHI   (2 * 96 * RSTRIDE)
#define OFF_BLO   (2 * 96 * RSTRIDE + 128 * RSTRIDE)
#define STAGE_SZ  (2 * 96 * RSTRIDE + 2 * 128 * RSTRIDE) // 50176
#define DYN_SZ    (2 * STAGE_SZ)                          // 100352

typedef unsigned long long ull;

// -------- device scratch --------
__device__ unsigned int g_present[B_ * PW];
__device__ unsigned int g_union[PW];
__device__ int   g_cidx[MAXC];
__device__ int   g_ntiles;
__device__ float g_h[R_ * D_];
__device__ __nv_bfloat16 g_h_hi[R_ * D_];
__device__ __nv_bfloat16 g_h_lo[R_ * D_];
__device__ float g_pm[NT * R_];
__device__ float g_ps[NT * R_];
__device__ int   g_pi[NT * R_];
__device__ float g_rownll[R_];
__device__ float g_rowacc[R_];
__device__ int   g_rowvalid[R_];

// -------- helpers --------
__device__ __forceinline__ uint32_t smem_u32(const void* p) {
    uint32_t a;
    asm("{ .reg .u64 t; cvta.to.shared.u64 t, %1; cvt.u32.u64 %0, t; }" : "=r"(a) : "l"(p));
    return a;
}

#define LDMATRIX_X4(r0, r1, r2, r3, addr) \
    asm volatile("ldmatrix.sync.aligned.m8n8.x4.shared.b16 {%0,%1,%2,%3}, [%4];" \
                 : "=r"(r0), "=r"(r1), "=r"(r2), "=r"(r3) : "r"(addr))

#define MMA16816(c0, c1, c2, c3, a0, a1, a2, a3, b0, b1) \
    asm volatile("mma.sync.aligned.m16n8k16.row.col.f32.bf16.bf16.f32 " \
                 "{%0,%1,%2,%3}, {%4,%5,%6,%7}, {%8,%9}, {%0,%1,%2,%3};" \
                 : "+f"(c0), "+f"(c1), "+f"(c2), "+f"(c3) \
                 : "r"(a0), "r"(a1), "r"(a2), "r"(a3), "r"(b0), "r"(b1))

#define CP_ASYNC16(dst_u32, src_ptr) \
    asm volatile("cp.async.ca.shared.global [%0], [%1], 16;" \
                 :: "r"(dst_u32), "l"(src_ptr) : "memory")
#define CP_COMMIT() asm volatile("cp.async.commit_group;" ::: "memory")
#define CP_WAIT0()  asm volatile("cp.async.wait_group 0;" ::: "memory")

__device__ __forceinline__ void sm_combine(float& m, float& s, int& bi,
                                           float m2, float s2, int bi2) {
    if (m2 > m) {
        s = s * __expf(m - m2) + s2;
        m = m2;
        bi = bi2;
    } else if (m2 == m) {
        s += s2;
        if (bi2 < bi) bi = bi2;
    } else {
        s += s2 * __expf(m2 - m);
    }
}

__device__ __forceinline__ void split_pair(float a, float b, unsigned& hi, unsigned& lo) {
    __nv_bfloat16 ah = __float2bfloat16_rn(a);
    __nv_bfloat16 bh = __float2bfloat16_rn(b);
    float ar = a - __bfloat162float(ah);
    float br = b - __bfloat162float(bh);
    __nv_bfloat16 al = __float2bfloat16_rn(ar);
    __nv_bfloat16 bl = __float2bfloat16_rn(br);
    hi = ((unsigned)__bfloat16_as_ushort(bh) << 16) | __bfloat16_as_ushort(ah);
    lo = ((unsigned)__bfloat16_as_ushort(bl) << 16) | __bfloat16_as_ushort(al);
}

// -------- small kernels --------
__global__ void zero_present_kernel() {
    int i = blockIdx.x * blockDim.x + threadIdx.x;
    if (i < B_ * PW) g_present[i] = 0u;
}

__global__ void scatter_kernel(const int* __restrict__ ids) {
    int i = blockIdx.x * blockDim.x + threadIdx.x;
    if (i < B_ * T_) {
        int b = i / T_;
        int tok = ids[i];
        if (tok >= 0 && tok < V_)
            atomicOr(&g_present[b * PW + (tok >> 5)], 1u << (tok & 31));
    }
}

__global__ void union_kernel() {
    int wi = blockIdx.x * blockDim.x + threadIdx.x;
    if (wi < PW) {
        unsigned u = 0;
#pragma unroll
        for (int b = 0; b < B_; b++) u |= g_present[b * PW + wi];
        g_union[wi] = u;
    }
}

// Single-block compaction: popcount prefix-scan of the union bitmap ->
// sorted index list g_cidx (ascending vocab order), padded with -1.
#define SCAN_T 512
__global__ void compact_kernel() {
    __shared__ int part[SCAN_T];
    const int t = threadIdx.x;
    unsigned wv[4];
    int cnt = 0;
    const int w0 = t * 4;
#pragma unroll
    for (int i = 0; i < 4; i++) {
        int wi = w0 + i;
        wv[i] = (wi < PW) ? g_union[wi] : 0u;
        cnt += __popc(wv[i]);
    }
    part[t] = cnt;
    __syncthreads();
    for (int off = 1; off < SCAN_T; off <<= 1) {
        int v = part[t];
        int add = (t >= off) ? part[t - off] : 0;
        __syncthreads();
        part[t] = v + add;
        __syncthreads();
    }
    int o = part[t] - cnt;              // exclusive offset
#pragma unroll
    for (int i = 0; i < 4; i++) {
        unsigned x = wv[i];
        int base = (w0 + i) * 32;
        while (x) {
            int bit = __ffs(x) - 1;
            g_cidx[o++] = base + bit;
            x &= x - 1;
        }
    }
    int total = part[SCAN_T - 1];
    int ntiles = (total + NTILE - 1) / NTILE;
    if (t == 0) g_ntiles = ntiles;
    int padEnd = ntiles * NTILE;
    for (int p = total + t; p < padEnd; p += SCAN_T) g_cidx[p] = -1;
}

__global__ void gather_kernel(const float* __restrict__ x,
                              const int* __restrict__ astarts) {
    int r = blockIdx.x;                 // 0..95
    int b = r & (B_ - 1);
    int tt = astarts[b] - 1;
    if (tt < 0) tt = 0;
    if (tt >= T_) tt = T_ - 1;
    const float* src = x + ((size_t)r * T_ + (size_t)tt) * D_;
    for (int d = threadIdx.x; d < D_; d += blockDim.x) {
        float f = src[d];
        g_h[r * D_ + d] = f;
        __nv_bfloat16 h = __float2bfloat16_rn(f);
        float lo = f - __bfloat162float(h);
        g_h_hi[r * D_ + d] = h;
        g_h_lo[r * D_ + d] = __float2bfloat16_rn(lo);
    }
}

// ---------------- HMMA GEMM over COMPACTED columns (persistent) ----------------
// Per tile: 96 rows x 128 compact vocab cols; acc = Ahi*Bhi + Ahi*Blo + Alo*Bhi.
__global__ void __launch_bounds__(256, 2) gemm_tc(const float* __restrict__ w) {
    extern __shared__ __align__(16) char dynsmem[];
    __shared__ int s_cidx[NTILE];
    const uint32_t base_u = smem_u32(dynsmem);

    const int t = threadIdx.x;
    const int wid = t >> 5, lane = t & 31;
    const int warp_m = wid >> 2;        // 0..1
    const int warp_n = wid & 3;         // 0..3
    const int g  = lane >> 2;           // 0..7
    const int tq = lane & 3;            // 0..3

    const int ti = lane >> 3;
    const int a_row  = (lane & 7) + ((ti & 1) << 3);
    const int a_koff = (ti >> 1) << 4;
    const int b_col  = (lane & 7) + ((ti >> 1) << 3);
    const int b_koff = (ti & 1) << 4;

    const int ntiles = g_ntiles;

    for (int tile = blockIdx.x; tile < ntiles; tile += gridDim.x) {
        const int vbase = tile * NTILE;

        if (t < NTILE) s_cidx[t] = g_cidx[vbase + t];
        __syncthreads();

        float acc[3][4][4];
#pragma unroll
        for (int i = 0; i < 3; i++)
#pragma unroll
            for (int j = 0; j < 4; j++)
#pragma unroll
                for (int k = 0; k < 4; k++) acc[i][j][k] = 0.f;

        // ---- prologue: stage chunk 0 ----
        {
            char* stg = dynsmem;
            const int k0 = 0;
#pragma unroll
            for (int i = 0; i < 3; i++) {
                int idx = t + i * 256;          // 0..767
                int half = idx >= 384;
                int j = idx - half * 384;
                int row = j >> 2, q = j & 3;
                const __nv_bfloat16* src =
                    (half ? g_h_lo : g_h_hi) + row * D_ + k0 + q * 8;
                uint32_t dst = base_u + (half ? OFF_ALO : OFF_AHI) +
                               (uint32_t)(row * RSTRIDE + q * 16);
                CP_ASYNC16(dst, src);
            }
            CP_COMMIT();
#pragma unroll
            for (int i = 0; i < 4; i++) {
                int idx = t + i * 256;          // 0..1023
                int n = idx >> 3, q = idx & 7;
                int v = s_cidx[n];
                float4 val = (v >= 0)
                    ? *reinterpret_cast<const float4*>(w + (size_t)v * D_ + k0 + q * 4)
                    : make_float4(0.f, 0.f, 0.f, 0.f);
                unsigned h01, l01, h23, l23;
                split_pair(val.x, val.y, h01, l01);
                split_pair(val.z, val.w, h23, l23);
                *reinterpret_cast<uint2*>(stg + OFF_BHI + n * RSTRIDE + q * 8) = make_uint2(h01, h23);
                *reinterpret_cast<uint2*>(stg + OFF_BLO + n * RSTRIDE + q * 8) = make_uint2(l01, l23);
            }
            CP_WAIT0();
        }
        __syncthreads();

        for (int c = 0; c < NCH; c++) {
            const int s = c & 1;
            const uint32_t stg_u = base_u + s * STAGE_SZ;
            const bool more = (c + 1 < NCH);

            float4 wreg[4];
            if (more) {
                const int k0 = (c + 1) * KC;
                const uint32_t st2 = base_u + (s ^ 1) * STAGE_SZ;
#pragma unroll
                for (int i = 0; i < 3; i++) {
                    int idx = t + i * 256;
                    int half = idx >= 384;
                    int j = idx - half * 384;
                    int row = j >> 2, q = j & 3;
                    const __nv_bfloat16* src =
                        (half ? g_h_lo : g_h_hi) + row * D_ + k0 + q * 8;
                    uint32_t dst = st2 + (half ? OFF_ALO : OFF_AHI) +
                                   (uint32_t)(row * RSTRIDE + q * 16);
                    CP_ASYNC16(dst, src);
                }
                CP_COMMIT();
#pragma unroll
                for (int i = 0; i < 4; i++) {
                    int idx = t + i * 256;
                    int n = idx >> 3, q = idx & 7;
                    int v = s_cidx[n];
                    wreg[i] = (v >= 0)
                        ? *reinterpret_cast<const float4*>(w + (size_t)v * D_ + k0 + q * 4)
                        : make_float4(0.f, 0.f, 0.f, 0.f);
                }
            }

            // ---- compute on chunk c ----
#pragma unroll
            for (int ks = 0; ks < 2; ks++) {
                const uint32_t kbyte = ks * 32;
                uint32_t bh[8], bl[8];
#pragma unroll
                for (int p = 0; p < 2; p++) {
                    uint32_t baddr = stg_u + OFF_BHI +
                        (uint32_t)(warp_n * 32 + p * 16 + b_col) * RSTRIDE + kbyte + b_koff;
                    LDMATRIX_X4(bh[p * 4 + 0], bh[p * 4 + 1], bh[p * 4 + 2], bh[p * 4 + 3], baddr);
                    LDMATRIX_X4(bl[p * 4 + 0], bl[p * 4 + 1], bl[p * 4 + 2], bl[p * 4 + 3],
                                baddr + (OFF_BLO - OFF_BHI));
                }
#pragma unroll
                for (int mf = 0; mf < 3; mf++) {
                    uint32_t aaddr = stg_u + OFF_AHI +
                        (uint32_t)(warp_m * 48 + mf * 16 + a_row) * RSTRIDE + kbyte + a_koff;
                    uint32_t ah0, ah1, ah2, ah3, al0, al1, al2, al3;
                    LDMATRIX_X4(ah0, ah1, ah2, ah3, aaddr);
                    LDMATRIX_X4(al0, al1, al2, al3, aaddr + (OFF_ALO - OFF_AHI));
#pragma unroll
                    for (int nf = 0; nf < 4; nf++) {
                        uint32_t b0h = bh[(nf >> 1) * 4 + (nf & 1) * 2 + 0];
                        uint32_t b1h = bh[(nf >> 1) * 4 + (nf & 1) * 2 + 1];
                        uint32_t b0l = bl[(nf >> 1) * 4 + (nf & 1) * 2 + 0];
                        uint32_t b1l = bl[(nf >> 1) * 4 + (nf & 1) * 2 + 1];
                        float* a4 = acc[mf][nf];
                        MMA16816(a4[0], a4[1], a4[2], a4[3], ah0, ah1, ah2, ah3, b0h, b1h);
                        MMA16816(a4[0], a4[1], a4[2], a4[3], ah0, ah1, ah2, ah3, b0l, b1l);
                        MMA16816(a4[0], a4[1], a4[2], a4[3], al0, al1, al2, al3, b0h, b1h);
                    }
                }
            }

            if (more) {
                char* stg2 = dynsmem + (s ^ 1) * STAGE_SZ;
#pragma unroll
                for (int i = 0; i < 4; i++) {
                    int idx = t + i * 256;
                    int n = idx >> 3, q = idx & 7;
                    unsigned h01, l01, h23, l23;
                    split_pair(wreg[i].x, wreg[i].y, h01, l01);
                    split_pair(wreg[i].z, wreg[i].w, h23, l23);
                    *reinterpret_cast<uint2*>(stg2 + OFF_BHI + n * RSTRIDE + q * 8) = make_uint2(h01, h23);
                    *reinterpret_cast<uint2*>(stg2 + OFF_BLO + n * RSTRIDE + q * 8) = make_uint2(l01, l23);
                }
                CP_WAIT0();
            }
            __syncthreads();
        }

        // ---- epilogue: park logits in smem (row stride 129 floats) ----
        float* lg = reinterpret_cast<float*>(dynsmem);
#pragma unroll
        for (int mf = 0; mf < 3; mf++) {
            int row0 = warp_m * 48 + mf * 16 + g;
#pragma unroll
            for (int nf = 0; nf < 4; nf++) {
                int col = warp_n * 32 + nf * 8 + tq * 2;
                lg[row0 * 129 + col]           = acc[mf][nf][0];
                lg[row0 * 129 + col + 1]       = acc[mf][nf][1];
                lg[(row0 + 8) * 129 + col]     = acc[mf][nf][2];
                lg[(row0 + 8) * 129 + col + 1] = acc[mf][nf][3];
            }
        }
        __syncthreads();

        // ---- masked online softmax + argmax, one thread per row ----
        if (t < R_) {
            int b = t & (B_ - 1);
            const unsigned int* pres = g_present + b * PW;
            const float* lrow = lg + t * 129;
            float mm = -INFINITY, ss = 0.f;
            int bi = 0x7fffffff;
            for (int cc = 0; cc < NTILE; cc++) {
                int v = s_cidx[cc];
                if (v >= 0 && ((pres[v >> 5] >> (v & 31)) & 1u))
                    sm_combine(mm, ss, bi, lrow[cc], 1.0f, v);
            }
            g_pm[tile * R_ + t] = mm;
            g_ps[tile * R_ + t] = ss;
            g_pi[tile * R_ + t] = bi;
        }
        __syncthreads();               // lg/s_cidx reuse by next tile
    }
}

// Per-row reduction over tile partials + tgt logit dot product.
__global__ void reduce_rows_kernel(const float* __restrict__ w,
                                   const int* __restrict__ tgts,
                                   const int* __restrict__ astarts) {
    __shared__ float smm[128], sms[128], sdot[128];
    __shared__ int smi[128];
    const int r = blockIdx.x;           // r = l*16 + b
    const int t = threadIdx.x;
    const int b = r & (B_ - 1);
    const int l = r >> 4;
    const int ntiles = g_ntiles;

    float m = -INFINITY, s = 0.f;
    int bi = 0x7fffffff;
    for (int tile = t; tile < ntiles; tile += 128)
        sm_combine(m, s, bi, g_pm[tile * R_ + r], g_ps[tile * R_ + r], g_pi[tile * R_ + r]);
    smm[t] = m; sms[t] = s; smi[t] = bi;

    int tgt = tgts[b * L_ + l];
    int tc = (tgt >= 0 && tgt < V_) ? tgt : 0;
    float dot = 0.f;
    for (int d = t; d < D_; d += 128)
        dot += w[(size_t)tc * D_ + d] * g_h[r * D_ + d];
    sdot[t] = dot;
    __syncthreads();

    for (int off = 64; off; off >>= 1) {
        if (t < off) {
            sm_combine(smm[t], sms[t], smi[t], smm[t + off], sms[t + off], smi[t + off]);
            sdot[t] += sdot[t + off];
        }
        __syncthreads();
    }

    if (t == 0) {
        float lse = smm[0] + logf(sms[0]);
        float nll = lse - sdot[0];
        int as = astarts[b];
        bool in_range = (as >= 1) && (as < T_);
        bool ptgt = (tgt >= 0 && tgt < V_) &&
                    ((g_present[b * PW + (tgt >> 5)] >> (tgt & 31)) & 1u);
        bool valid = ptgt && in_range;
        int pred = smi[0];
        g_rownll[r]   = valid ? nll : 0.f;
        g_rowacc[r]   = (valid && pred == tgt) ? 1.f : 0.f;
        g_rowvalid[r] = valid ? 1 : 0;
    }
}

__global__ void finalize_kernel(float* __restrict__ out) {
    if (threadIdx.x == 0) {
        float avg_loss = 0.f, avg_acc = 0.f, final_acc = 0.f;
        int nhas = 0;
        for (int l = 0; l < L_; l++) {
            float cnt = 0.f, sl = 0.f, sa = 0.f;
            for (int b = 0; b < B_; b++) {
                int r = l * B_ + b;
                cnt += (float)g_rowvalid[r];
                sl  += g_rownll[r];
                sa  += g_rowacc[r];
            }
            float denom = fmaxf(cnt, 1.f);
            float ll = sl / denom;
            float la = sa / denom;
            if (cnt > 0.f) { nhas++; avg_loss += ll; avg_acc += la; }
            if (l == L_ - 1) final_acc = la;
        }
        float nv = fmaxf((float)nhas, 1.f);
        out[0] = avg_loss / nv;
        out[1] = avg_acc / nv;
        out[2] = final_acc;
    }
}

extern "C" void kernel_launch(void* const* d_in, const int* in_sizes, int n_in,
                              void* d_out, int out_size) {
    const float* x = nullptr;
    const float* w = nullptr;
    const int* ids = nullptr;
    const int* tgts = nullptr;
    const int* astarts = nullptr;
    for (int i = 0; i < n_in; i++) {
        long sz = (long)in_sizes[i];
        if (sz == (long)L_ * B_ * T_ * D_)      x = (const float*)d_in[i];
        else if (sz == (long)V_ * D_)           w = (const float*)d_in[i];
        else if (sz == (long)B_ * T_)           ids = (const int*)d_in[i];
        else if (sz == (long)B_ * L_)           tgts = (const int*)d_in[i];
        else if (sz == (long)B_)                astarts = (const int*)d_in[i];
    }

    static int attr_set = 0;
    if (!attr_set) {
        cudaFuncSetAttribute(gemm_tc, cudaFuncAttributeMaxDynamicSharedMemorySize, DYN_SZ);
        attr_set = 1;
    }

    zero_present_kernel<<<(B_ * PW + 255) / 256, 256>>>();
    scatter_kernel<<<(B_ * T_ + 255) / 256, 256>>>(ids);
    union_kernel<<<(PW + 255) / 256, 256>>>();
    compact_kernel<<<1, SCAN_T>>>();
    gather_kernel<<<R_, 256>>>(x, astarts);
    gemm_tc<<<GRID_P, 256, DYN_SZ>>>(w);
    reduce_rows_kernel<<<R_, 128>>>(w, tgts, astarts);
    finalize_kernel<<<1, 32>>>((float*)d_out);
}

// round 10
// speedup vs baseline: 3.6467x; 1.1088x over previous
#include <cuda_runtime.h>
#include <cuda_bf16.h>
#include <math.h>
#include <stdint.h>

// Problem constants
#define L_  6
#define B_  16
#define T_  2048
#define D_  768
#define V_  50280
#define R_  96               // L_*B_ rows
#define PW  1572             // ceil(V_/32) bitmap words per batch row

// GEMM tiling (mma.sync m16n8k16 bf16, hi/lo split)
#define NTILE 128            // vocab per CTA tile
#define NT    393            // max tiles (full V) — partial arrays sized for this
#define KC    32             // K chunk
#define NCH   (D_ / KC)      // 24
#define GRID_P 296           // persistent grid: 148 SMs x 2 CTAs
#define MAXC  33024          // max compacted columns (<= B*T) + pad

// Compaction grid
#define CB    128
#define NCB   ((PW + CB - 1) / CB)   // 13

// Padded smem rows: 56 bf16 = 112 B (16B-aligned, conflict-free ldmatrix)
#define RSTRIDE   112
#define OFF_AHI   0
#define OFF_ALO   (96 * RSTRIDE)
#define OFF_BHI   (2 * 96 * RSTRIDE)
#define OFF_BLO   (2 * 96 * RSTRIDE + 128 * RSTRIDE)
#define STAGE_SZ  (2 * 96 * RSTRIDE + 2 * 128 * RSTRIDE) // 50176
#define DYN_SZ    (2 * STAGE_SZ)                          // 100352

typedef unsigned long long ull;

// -------- device scratch --------
__device__ unsigned int g_present[B_ * PW];
__device__ unsigned int g_union[PW];
__device__ int   g_bcnt[NCB];
__device__ int   g_cidx[MAXC];
__device__ int   g_ccount;
__device__ float g_h[R_ * D_];
__device__ __nv_bfloat16 g_h_hi[R_ * D_];
__device__ __nv_bfloat16 g_h_lo[R_ * D_];
__device__ float g_pm[NT * R_];
__device__ float g_ps[NT * R_];
__device__ int   g_pi[NT * R_];
__device__ float g_rownll[R_];
__device__ float g_rowacc[R_];
__device__ int   g_rowvalid[R_];

// -------- helpers --------
__device__ __forceinline__ uint32_t smem_u32(const void* p) {
    uint32_t a;
    asm("{ .reg .u64 t; cvta.to.shared.u64 t, %1; cvt.u32.u64 %0, t; }" : "=r"(a) : "l"(p));
    return a;
}

#define LDMATRIX_X4(r0, r1, r2, r3, addr) \
    asm volatile("ldmatrix.sync.aligned.m8n8.x4.shared.b16 {%0,%1,%2,%3}, [%4];" \
                 : "=r"(r0), "=r"(r1), "=r"(r2), "=r"(r3) : "r"(addr))

#define MMA16816(c0, c1, c2, c3, a0, a1, a2, a3, b0, b1) \
    asm volatile("mma.sync.aligned.m16n8k16.row.col.f32.bf16.bf16.f32 " \
                 "{%0,%1,%2,%3}, {%4,%5,%6,%7}, {%8,%9}, {%0,%1,%2,%3};" \
                 : "+f"(c0), "+f"(c1), "+f"(c2), "+f"(c3) \
                 : "r"(a0), "r"(a1), "r"(a2), "r"(a3), "r"(b0), "r"(b1))

#define CP_ASYNC16(dst_u32, src_ptr) \
    asm volatile("cp.async.ca.shared.global [%0], [%1], 16;" \
                 :: "r"(dst_u32), "l"(src_ptr) : "memory")
#define CP_COMMIT() asm volatile("cp.async.commit_group;" ::: "memory")
#define CP_WAIT0()  asm volatile("cp.async.wait_group 0;" ::: "memory")

__device__ __forceinline__ void sm_combine(float& m, float& s, int& bi,
                                           float m2, float s2, int bi2) {
    if (m2 > m) {
        s = s * __expf(m - m2) + s2;
        m = m2;
        bi = bi2;
    } else if (m2 == m) {
        s += s2;
        if (bi2 < bi) bi = bi2;
    } else {
        s += s2 * __expf(m2 - m);
    }
}

__device__ __forceinline__ void split_pair(float a, float b, unsigned& hi, unsigned& lo) {
    __nv_bfloat16 ah = __float2bfloat16_rn(a);
    __nv_bfloat16 bh = __float2bfloat16_rn(b);
    float ar = a - __bfloat162float(ah);
    float br = b - __bfloat162float(bh);
    __nv_bfloat16 al = __float2bfloat16_rn(ar);
    __nv_bfloat16 bl = __float2bfloat16_rn(br);
    hi = ((unsigned)__bfloat16_as_ushort(bh) << 16) | __bfloat16_as_ushort(ah);
    lo = ((unsigned)__bfloat16_as_ushort(bl) << 16) | __bfloat16_as_ushort(al);
}

// -------- small kernels --------
__global__ void zero_present_kernel() {
    int i = blockIdx.x * blockDim.x + threadIdx.x;
    if (i < B_ * PW) g_present[i] = 0u;
    if (i < PW) g_union[i] = 0u;
}

// scatter also builds the union bitmap directly
__global__ void scatter_kernel(const int* __restrict__ ids) {
    int i = blockIdx.x * blockDim.x + threadIdx.x;
    if (i < B_ * T_) {
        int b = i / T_;
        int tok = ids[i];
        if (tok >= 0 && tok < V_) {
            unsigned bit = 1u << (tok & 31);
            atomicOr(&g_present[b * PW + (tok >> 5)], bit);
            atomicOr(&g_union[tok >> 5], bit);
        }
    }
}

// Pass 1: per-block popcounts
__global__ void compact_count() {
    __shared__ int wsum[CB / 32];
    int wi = blockIdx.x * CB + threadIdx.x;
    unsigned wv = (wi < PW) ? g_union[wi] : 0u;
    int cnt = __popc(wv);
    int lane = threadIdx.x & 31, wwid = threadIdx.x >> 5;
#pragma unroll
    for (int o = 16; o; o >>= 1) cnt += __shfl_down_sync(~0u, cnt, o);
    if (lane == 0) wsum[wwid] = cnt;
    __syncthreads();
    if (threadIdx.x == 0) {
        int s = 0;
#pragma unroll
        for (int i = 0; i < CB / 32; i++) s += wsum[i];
        g_bcnt[blockIdx.x] = s;
    }
}

// Pass 2: deterministic ascending-order write using prefix of block counts
__global__ void compact_write() {
    __shared__ int wsum[CB / 32];
    __shared__ int bbase;
    const int t = threadIdx.x;
    int lane = t & 31, wwid = t >> 5;
    if (t == 0) {
        int s = 0;
        for (int i = 0; i < NCB; i++) {
            if (i == (int)blockIdx.x) bbase = s;
            s += g_bcnt[i];
        }
        if (blockIdx.x == 0) g_ccount = s;
    }
    int wi = blockIdx.x * CB + t;
    unsigned wv = (wi < PW) ? g_union[wi] : 0u;
    int cnt = __popc(wv);
    int scan = cnt;
#pragma unroll
    for (int o = 1; o < 32; o <<= 1) {
        int v = __shfl_up_sync(~0u, scan, o);
        if (lane >= o) scan += v;
    }
    if (lane == 31) wsum[wwid] = scan;
    __syncthreads();
    int woff = 0;
    for (int i = 0; i < wwid; i++) woff += wsum[i];
    int off = bbase + woff + scan - cnt;
    int base = wi * 32;
    while (wv) {
        int bit = __ffs(wv) - 1;
        g_cidx[off++] = base + bit;
        wv &= wv - 1;
    }
}

__global__ void gather_kernel(const float* __restrict__ x,
                              const int* __restrict__ astarts) {
    int r = blockIdx.x;                 // 0..95
    int b = r & (B_ - 1);
    int tt = astarts[b] - 1;
    if (tt < 0) tt = 0;
    if (tt >= T_) tt = T_ - 1;
    const float* src = x + ((size_t)r * T_ + (size_t)tt) * D_;
    for (int d = threadIdx.x; d < D_; d += blockDim.x) {
        float f = src[d];
        g_h[r * D_ + d] = f;
        __nv_bfloat16 h = __float2bfloat16_rn(f);
        float lo = f - __bfloat162float(h);
        g_h_hi[r * D_ + d] = h;
        g_h_lo[r * D_ + d] = __float2bfloat16_rn(lo);
    }
}

// ---------------- HMMA GEMM over COMPACTED columns (persistent) ----------------
__global__ void __launch_bounds__(256, 2) gemm_tc(const float* __restrict__ w) {
    extern __shared__ __align__(16) char dynsmem[];
    __shared__ int s_cidx[NTILE];
    const uint32_t base_u = smem_u32(dynsmem);

    const int t = threadIdx.x;
    const int wid = t >> 5, lane = t & 31;
    const int warp_m = wid >> 2;        // 0..1
    const int warp_n = wid & 3;         // 0..3
    const int g  = lane >> 2;           // 0..7
    const int tq = lane & 3;            // 0..3

    const int ti = lane >> 3;
    const int a_row  = (lane & 7) + ((ti & 1) << 3);
    const int a_koff = (ti >> 1) << 4;
    const int b_col  = (lane & 7) + ((ti >> 1) << 3);
    const int b_koff = (ti & 1) << 4;

    const int total = g_ccount;
    const int ntiles = (total + NTILE - 1) / NTILE;

    for (int tile = blockIdx.x; tile < ntiles; tile += gridDim.x) {
        const int vbase = tile * NTILE;

        if (t < NTILE) {
            int gi = vbase + t;
            s_cidx[t] = (gi < total) ? g_cidx[gi] : -1;
        }
        __syncthreads();

        float acc[3][4][4];
#pragma unroll
        for (int i = 0; i < 3; i++)
#pragma unroll
            for (int j = 0; j < 4; j++)
#pragma unroll
                for (int k = 0; k < 4; k++) acc[i][j][k] = 0.f;

        // ---- prologue: stage chunk 0 ----
        {
            char* stg = dynsmem;
            const int k0 = 0;
#pragma unroll
            for (int i = 0; i < 3; i++) {
                int idx = t + i * 256;          // 0..767
                int half = idx >= 384;
                int j = idx - half * 384;
                int row = j >> 2, q = j & 3;
                const __nv_bfloat16* src =
                    (half ? g_h_lo : g_h_hi) + row * D_ + k0 + q * 8;
                uint32_t dst = base_u + (half ? OFF_ALO : OFF_AHI) +
                               (uint32_t)(row * RSTRIDE + q * 16);
                CP_ASYNC16(dst, src);
            }
            CP_COMMIT();
#pragma unroll
            for (int i = 0; i < 4; i++) {
                int idx = t + i * 256;          // 0..1023
                int n = idx >> 3, q = idx & 7;
                int v = s_cidx[n];
                float4 val = (v >= 0)
                    ? *reinterpret_cast<const float4*>(w + (size_t)v * D_ + k0 + q * 4)
                    : make_float4(0.f, 0.f, 0.f, 0.f);
                unsigned h01, l01, h23, l23;
                split_pair(val.x, val.y, h01, l01);
                split_pair(val.z, val.w, h23, l23);
                *reinterpret_cast<uint2*>(stg + OFF_BHI + n * RSTRIDE + q * 8) = make_uint2(h01, h23);
                *reinterpret_cast<uint2*>(stg + OFF_BLO + n * RSTRIDE + q * 8) = make_uint2(l01, l23);
            }
            CP_WAIT0();
        }
        __syncthreads();

        for (int c = 0; c < NCH; c++) {
            const int s = c & 1;
            const uint32_t stg_u = base_u + s * STAGE_SZ;
            const bool more = (c + 1 < NCH);

            float4 wreg[4];
            if (more) {
                const int k0 = (c + 1) * KC;
                const uint32_t st2 = base_u + (s ^ 1) * STAGE_SZ;
#pragma unroll
                for (int i = 0; i < 3; i++) {
                    int idx = t + i * 256;
                    int half = idx >= 384;
                    int j = idx - half * 384;
                    int row = j >> 2, q = j & 3;
                    const __nv_bfloat16* src =
                        (half ? g_h_lo : g_h_hi) + row * D_ + k0 + q * 8;
                    uint32_t dst = st2 + (half ? OFF_ALO : OFF_AHI) +
                                   (uint32_t)(row * RSTRIDE + q * 16);
                    CP_ASYNC16(dst, src);
                }
                CP_COMMIT();
#pragma unroll
                for (int i = 0; i < 4; i++) {
                    int idx = t + i * 256;
                    int n = idx >> 3, q = idx & 7;
                    int v = s_cidx[n];
                    wreg[i] = (v >= 0)
                        ? *reinterpret_cast<const float4*>(w + (size_t)v * D_ + k0 + q * 4)
                        : make_float4(0.f, 0.f, 0.f, 0.f);
                }
            }

            // ---- compute on chunk c ----
#pragma unroll
            for (int ks = 0; ks < 2; ks++) {
                const uint32_t kbyte = ks * 32;
                uint32_t bh[8], bl[8];
#pragma unroll
                for (int p = 0; p < 2; p++) {
                    uint32_t baddr = stg_u + OFF_BHI +
                        (uint32_t)(warp_n * 32 + p * 16 + b_col) * RSTRIDE + kbyte + b_koff;
                    LDMATRIX_X4(bh[p * 4 + 0], bh[p * 4 + 1], bh[p * 4 + 2], bh[p * 4 + 3], baddr);
                    LDMATRIX_X4(bl[p * 4 + 0], bl[p * 4 + 1], bl[p * 4 + 2], bl[p * 4 + 3],
                                baddr + (OFF_BLO - OFF_BHI));
                }
#pragma unroll
                for (int mf = 0; mf < 3; mf++) {
                    uint32_t aaddr = stg_u + OFF_AHI +
                        (uint32_t)(warp_m * 48 + mf * 16 + a_row) * RSTRIDE + kbyte + a_koff;
                    uint32_t ah0, ah1, ah2, ah3, al0, al1, al2, al3;
                    LDMATRIX_X4(ah0, ah1, ah2, ah3, aaddr);
                    LDMATRIX_X4(al0, al1, al2, al3, aaddr + (OFF_ALO - OFF_AHI));
#pragma unroll
                    for (int nf = 0; nf < 4; nf++) {
                        uint32_t b0h = bh[(nf >> 1) * 4 + (nf & 1) * 2 + 0];
                        uint32_t b1h = bh[(nf >> 1) * 4 + (nf & 1) * 2 + 1];
                        uint32_t b0l = bl[(nf >> 1) * 4 + (nf & 1) * 2 + 0];
                        uint32_t b1l = bl[(nf >> 1) * 4 + (nf & 1) * 2 + 1];
                        float* a4 = acc[mf][nf];
                        MMA16816(a4[0], a4[1], a4[2], a4[3], ah0, ah1, ah2, ah3, b0h, b1h);
                        MMA16816(a4[0], a4[1], a4[2], a4[3], ah0, ah1, ah2, ah3, b0l, b1l);
                        MMA16816(a4[0], a4[1], a4[2], a4[3], al0, al1, al2, al3, b0h, b1h);
                    }
                }
            }

            if (more) {
                char* stg2 = dynsmem + (s ^ 1) * STAGE_SZ;
#pragma unroll
                for (int i = 0; i < 4; i++) {
                    int idx = t + i * 256;
                    int n = idx >> 3, q = idx & 7;
                    unsigned h01, l01, h23, l23;
                    split_pair(wreg[i].x, wreg[i].y, h01, l01);
                    split_pair(wreg[i].z, wreg[i].w, h23, l23);
                    *reinterpret_cast<uint2*>(stg2 + OFF_BHI + n * RSTRIDE + q * 8) = make_uint2(h01, h23);
                    *reinterpret_cast<uint2*>(stg2 + OFF_BLO + n * RSTRIDE + q * 8) = make_uint2(l01, l23);
                }
                CP_WAIT0();
            }
            __syncthreads();
        }

        // ---- epilogue: park logits in smem (row stride 129 floats) ----
        float* lg = reinterpret_cast<float*>(dynsmem);
#pragma unroll
        for (int mf = 0; mf < 3; mf++) {
            int row0 = warp_m * 48 + mf * 16 + g;
#pragma unroll
            for (int nf = 0; nf < 4; nf++) {
                int col = warp_n * 32 + nf * 8 + tq * 2;
                lg[row0 * 129 + col]           = acc[mf][nf][0];
                lg[row0 * 129 + col + 1]       = acc[mf][nf][1];
                lg[(row0 + 8) * 129 + col]     = acc[mf][nf][2];
                lg[(row0 + 8) * 129 + col + 1] = acc[mf][nf][3];
            }
        }
        __syncthreads();

        // ---- masked online softmax + argmax, one thread per row ----
        if (t < R_) {
            int b = t & (B_ - 1);
            const unsigned int* pres = g_present + b * PW;
            const float* lrow = lg + t * 129;
            float mm = -INFINITY, ss = 0.f;
            int bi = 0x7fffffff;
            for (int cc = 0; cc < NTILE; cc++) {
                int v = s_cidx[cc];
                if (v >= 0 && ((pres[v >> 5] >> (v & 31)) & 1u))
                    sm_combine(mm, ss, bi, lrow[cc], 1.0f, v);
            }
            g_pm[tile * R_ + t] = mm;
            g_ps[tile * R_ + t] = ss;
            g_pi[tile * R_ + t] = bi;
        }
        __syncthreads();               // lg/s_cidx reuse by next tile
    }
}

// Per-row reduction over tile partials + tgt logit dot product.
__global__ void reduce_rows_kernel(const float* __restrict__ w,
                                   const int* __restrict__ tgts,
                                   const int* __restrict__ astarts) {
    __shared__ float smm[128], sms[128], sdot[128];
    __shared__ int smi[128];
    const int r = blockIdx.x;           // r = l*16 + b
    const int t = threadIdx.x;
    const int b = r & (B_ - 1);
    const int l = r >> 4;
    const int ntiles = (g_ccount + NTILE - 1) / NTILE;

    float m = -INFINITY, s = 0.f;
    int bi = 0x7fffffff;
    for (int tile = t; tile < ntiles; tile += 128)
        sm_combine(m, s, bi, g_pm[tile * R_ + r], g_ps[tile * R_ + r], g_pi[tile * R_ + r]);
    smm[t] = m; sms[t] = s; smi[t] = bi;

    int tgt = tgts[b * L_ + l];
    int tc = (tgt >= 0 && tgt < V_) ? tgt : 0;
    float dot = 0.f;
    for (int d = t; d < D_; d += 128)
        dot += w[(size_t)tc * D_ + d] * g_h[r * D_ + d];
    sdot[t] = dot;
    __syncthreads();

    for (int off = 64; off; off >>= 1) {
        if (t < off) {
            sm_combine(smm[t], sms[t], smi[t], smm[t + off], sms[t + off], smi[t + off]);
            sdot[t] += sdot[t + off];
        }
        __syncthreads();
    }

    if (t == 0) {
        float lse = smm[0] + logf(sms[0]);
        float nll = lse - sdot[0];
        int as = astarts[b];
        bool in_range = (as >= 1) && (as < T_);
        bool ptgt = (tgt >= 0 && tgt < V_) &&
                    ((g_present[b * PW + (tgt >> 5)] >> (tgt & 31)) & 1u);
        bool valid = ptgt && in_range;
        int pred = smi[0];
        g_rownll[r]   = valid ? nll : 0.f;
        g_rowacc[r]   = (valid && pred == tgt) ? 1.f : 0.f;
        g_rowvalid[r] = valid ? 1 : 0;
    }
}

__global__ void finalize_kernel(float* __restrict__ out) {
    if (threadIdx.x == 0) {
        float avg_loss = 0.f, avg_acc = 0.f, final_acc = 0.f;
        int nhas = 0;
        for (int l = 0; l < L_; l++) {
            float cnt = 0.f, sl = 0.f, sa = 0.f;
            for (int b = 0; b < B_; b++) {
                int r = l * B_ + b;
                cnt += (float)g_rowvalid[r];
                sl  += g_rownll[r];
                sa  += g_rowacc[r];
            }
            float denom = fmaxf(cnt, 1.f);
            float ll = sl / denom;
            float la = sa / denom;
            if (cnt > 0.f) { nhas++; avg_loss += ll; avg_acc += la; }
            if (l == L_ - 1) final_acc = la;
        }
        float nv = fmaxf((float)nhas, 1.f);
        out[0] = avg_loss / nv;
        out[1] = avg_acc / nv;
        out[2] = final_acc;
    }
}

extern "C" void kernel_launch(void* const* d_in, const int* in_sizes, int n_in,
                              void* d_out, int out_size) {
    const float* x = nullptr;
    const float* w = nullptr;
    const int* ids = nullptr;
    const int* tgts = nullptr;
    const int* astarts = nullptr;
    for (int i = 0; i < n_in; i++) {
        long sz = (long)in_sizes[i];
        if (sz == (long)L_ * B_ * T_ * D_)      x = (const float*)d_in[i];
        else if (sz == (long)V_ * D_)           w = (const float*)d_in[i];
        else if (sz == (long)B_ * T_)           ids = (const int*)d_in[i];
        else if (sz == (long)B_ * L_)           tgts = (const int*)d_in[i];
        else if (sz == (long)B_)                astarts = (const int*)d_in[i];
    }

    static int attr_set = 0;
    if (!attr_set) {
        cudaFuncSetAttribute(gemm_tc, cudaFuncAttributeMaxDynamicSharedMemorySize, DYN_SZ);
        attr_set = 1;
    }

    zero_present_kernel<<<(B_ * PW + 255) / 256, 256>>>();
    scatter_kernel<<<(B_ * T_ + 255) / 256, 256>>>(ids);
    compact_count<<<NCB, CB>>>();
    compact_write<<<NCB, CB>>>();
    gather_kernel<<<R_, 256>>>(x, astarts);
    gemm_tc<<<GRID_P, 256, DYN_SZ>>>(w);
    reduce_rows_kernel<<<R_, 128>>>(w, tgts, astarts);
    finalize_kernel<<<1, 32>>>((float*)d_out);
}

// round 14
// speedup vs baseline: 6.9029x; 1.8929x over previous
#include <cuda_runtime.h>
#include <math.h>
#include <stdint.h>

// Problem constants
#define L_  6
#define B_  16
#define T_  2048
#define D_  768
#define V_  50280
#define R_  96               // L_*B_ rows
#define PW  1572             // ceil(V_/32) bitmap words per batch row

// Per-batch gather-dot GEMM
#define BPB   8              // column blocks per batch
#define CTILE 256            // columns per block
#define NP    (B_ * BPB)     // 128 partials

// Compaction grid
#define CB    128
#define NCB   ((PW + CB - 1) / CB)   // 13

// -------- device scratch --------
__device__ unsigned int g_present[B_ * PW];
__device__ int   g_bcnt13[B_ * NCB];
__device__ int   g_bcount[B_];
__device__ int   g_bidx[B_ * 2048];
__device__ float g_h[R_ * D_];
__device__ float g_pm[NP * 6];
__device__ float g_ps[NP * 6];
__device__ int   g_pi[NP * 6];
__device__ float g_rownll[R_];
__device__ float g_rowacc[R_];
__device__ int   g_rowvalid[R_];

// online-softmax + first-occurrence-argmax merge
__device__ __forceinline__ void sm_combine(float& m, float& s, int& bi,
                                           float m2, float s2, int bi2) {
    if (m2 > m) {
        s = s * __expf(m - m2) + s2;
        m = m2;
        bi = bi2;
    } else if (m2 == m) {
        s += s2;
        if (bi2 < bi) bi = bi2;
    } else {
        s += s2 * __expf(m2 - m);
    }
}

// -------- small kernels --------
__global__ void zero_present_kernel() {
    int i = blockIdx.x * blockDim.x + threadIdx.x;
    if (i < B_ * PW) g_present[i] = 0u;
}

__global__ void scatter_kernel(const int* __restrict__ ids) {
    int i = blockIdx.x * blockDim.x + threadIdx.x;
    if (i < B_ * T_) {
        int b = i / T_;
        int tok = ids[i];
        if (tok >= 0 && tok < V_)
            atomicOr(&g_present[b * PW + (tok >> 5)], 1u << (tok & 31));
    }
}

// Pass 1: per-(batch, word-block) popcounts
__global__ void bcount_kernel() {
    __shared__ int ws[CB / 32];
    int b = blockIdx.y, i = blockIdx.x, t = threadIdx.x;
    int wi = i * CB + t;
    unsigned wv = (wi < PW) ? g_present[b * PW + wi] : 0u;
    int c = __popc(wv);
    int lane = t & 31, wd = t >> 5;
#pragma unroll
    for (int o = 16; o; o >>= 1) c += __shfl_down_sync(~0u, c, o);
    if (lane == 0) ws[wd] = c;
    __syncthreads();
    if (t == 0) {
        int s = 0;
#pragma unroll
        for (int k = 0; k < CB / 32; k++) s += ws[k];
        g_bcnt13[b * NCB + i] = s;
    }
}

// Pass 2: deterministic ascending-order per-batch index list
__global__ void bwrite_kernel() {
    __shared__ int ws[CB / 32];
    __shared__ int bbase;
    int b = blockIdx.y, i = blockIdx.x, t = threadIdx.x;
    int lane = t & 31, wd = t >> 5;
    if (t == 0) {
        int s = 0;
        for (int k = 0; k < NCB; k++) {
            if (k == i) bbase = s;
            s += g_bcnt13[b * NCB + k];
        }
        if (i == 0) g_bcount[b] = s;
    }
    __syncthreads();
    int wi = i * CB + t;
    unsigned wv = (wi < PW) ? g_present[b * PW + wi] : 0u;
    int cnt = __popc(wv);
    int scan = cnt;
#pragma unroll
    for (int o = 1; o < 32; o <<= 1) {
        int v = __shfl_up_sync(~0u, scan, o);
        if (lane >= o) scan += v;
    }
    if (lane == 31) ws[wd] = scan;
    __syncthreads();
    int woff = 0;
    for (int k = 0; k < wd; k++) woff += ws[k];
    int off = bbase + woff + scan - cnt;
    int base = wi * 32;
    while (wv) {
        int bit = __ffs(wv) - 1;
        g_bidx[b * 2048 + off] = base + bit;
        off++;
        wv &= wv - 1;
    }
}

__global__ void gather_kernel(const float* __restrict__ x,
                              const int* __restrict__ astarts) {
    int r = blockIdx.x;                 // 0..95
    int b = r & (B_ - 1);
    int tt = astarts[b] - 1;
    if (tt < 0) tt = 0;
    if (tt >= T_) tt = T_ - 1;
    const float* src = x + ((size_t)r * T_ + (size_t)tt) * D_;
    for (int d = threadIdx.x; d < D_; d += blockDim.x)
        g_h[r * D_ + d] = src[d];
}

// ---------------- per-batch gather-dot GEMM + fused softmax/argmax ----------
// Block p: batch b = p/8, column block blk = p%8 -> columns [blk*256, +256).
// Warp computes 4 columns/iter: 6-row x 4-col fp32 dots over D=768.
__global__ void __launch_bounds__(256, 1) gemm_dot(const float* __restrict__ w) {
    __shared__ float s_h[6][D_];
    __shared__ int   s_idx[CTILE];
    __shared__ float s_lg[6][32];
    __shared__ float s_fm[192], s_fs[192];
    __shared__ int   s_fb[192];

    const int p = blockIdx.x;
    const int b = p >> 3, blk = p & 7;
    const int t = threadIdx.x, wid = t >> 5, lane = t & 31;
    const int cnt = g_bcount[b];
    const int cstart = blk * CTILE;

    // load h rows (float4) and column indices
    for (int i = t; i < 6 * (D_ / 4); i += 256) {
        int l = i / (D_ / 4), d4 = i % (D_ / 4);
        reinterpret_cast<float4*>(s_h[l])[d4] =
            reinterpret_cast<const float4*>(g_h + (l * B_ + b) * D_)[d4];
    }
    {
        int gi = cstart + t;
        s_idx[t] = (gi < cnt) ? g_bidx[b * 2048 + gi] : -1;
    }
    __syncthreads();

    // per-thread online state (valid for t < 192: row = t>>5, col = t&31)
    float m1 = -INFINITY, s1 = 0.f;
    int b1 = 0x7fffffff;

#pragma unroll 1
    for (int iter = 0; iter < CTILE / 32; iter++) {
        const int cb = iter * 32 + wid * 4;
        int v0 = s_idx[cb], v1 = s_idx[cb + 1], v2 = s_idx[cb + 2], v3 = s_idx[cb + 3];
        const float* w0 = w + (size_t)(v0 < 0 ? 0 : v0) * D_;
        const float* w1 = w + (size_t)(v1 < 0 ? 0 : v1) * D_;
        const float* w2 = w + (size_t)(v2 < 0 ? 0 : v2) * D_;
        const float* w3 = w + (size_t)(v3 < 0 ? 0 : v3) * D_;

        float acc[6][4];
#pragma unroll
        for (int l = 0; l < 6; l++)
#pragma unroll
            for (int j = 0; j < 4; j++) acc[l][j] = 0.f;

#pragma unroll
        for (int i = 0; i < 6; i++) {
            int d = i * 128 + lane * 4;
            float4 a = *reinterpret_cast<const float4*>(w0 + d);
            float4 c = *reinterpret_cast<const float4*>(w1 + d);
            float4 e = *reinterpret_cast<const float4*>(w2 + d);
            float4 f = *reinterpret_cast<const float4*>(w3 + d);
#pragma unroll
            for (int l = 0; l < 6; l++) {
                float4 h4 = *reinterpret_cast<const float4*>(&s_h[l][d]);
                acc[l][0] = fmaf(h4.x, a.x, fmaf(h4.y, a.y, fmaf(h4.z, a.z, fmaf(h4.w, a.w, acc[l][0]))));
                acc[l][1] = fmaf(h4.x, c.x, fmaf(h4.y, c.y, fmaf(h4.z, c.z, fmaf(h4.w, c.w, acc[l][1]))));
                acc[l][2] = fmaf(h4.x, e.x, fmaf(h4.y, e.y, fmaf(h4.z, e.z, fmaf(h4.w, e.w, acc[l][2]))));
                acc[l][3] = fmaf(h4.x, f.x, fmaf(h4.y, f.y, fmaf(h4.z, f.z, fmaf(h4.w, f.w, acc[l][3]))));
            }
        }
        // reduce each accumulator to lane 0
#pragma unroll
        for (int l = 0; l < 6; l++)
#pragma unroll
            for (int j = 0; j < 4; j++)
#pragma unroll
                for (int o = 16; o; o >>= 1)
                    acc[l][j] += __shfl_down_sync(~0u, acc[l][j], o);
        if (lane == 0) {
#pragma unroll
            for (int l = 0; l < 6; l++) {
                s_lg[l][wid * 4 + 0] = acc[l][0];
                s_lg[l][wid * 4 + 1] = acc[l][1];
                s_lg[l][wid * 4 + 2] = acc[l][2];
                s_lg[l][wid * 4 + 3] = acc[l][3];
            }
        }
        __syncthreads();
        if (t < 192) {
            int row = t >> 5, col = t & 31;
            int v = s_idx[iter * 32 + col];
            if (v >= 0) sm_combine(m1, s1, b1, s_lg[row][col], 1.0f, v);
        }
        __syncthreads();
    }

    if (t < 192) { s_fm[t] = m1; s_fs[t] = s1; s_fb[t] = b1; }
    __syncthreads();
    if (t < 6) {
        float mm = -INFINITY, ss = 0.f;
        int bb = 0x7fffffff;
        for (int col = 0; col < 32; col++) {
            int k = t * 32 + col;
            sm_combine(mm, ss, bb, s_fm[k], s_fs[k], s_fb[k]);
        }
        g_pm[p * 6 + t] = mm;
        g_ps[p * 6 + t] = ss;
        g_pi[p * 6 + t] = bb;
    }
}

// Per-row: merge 8 block partials + tgt logit dot product.
__global__ void reduce_rows_kernel(const float* __restrict__ w,
                                   const int* __restrict__ tgts,
                                   const int* __restrict__ astarts) {
    __shared__ float sdot[128];
    const int r = blockIdx.x;           // r = l*16 + b
    const int t = threadIdx.x;
    const int b = r & (B_ - 1);
    const int l = r >> 4;

    int tgt = tgts[b * L_ + l];
    int tc = (tgt >= 0 && tgt < V_) ? tgt : 0;
    float dot = 0.f;
    for (int d = t; d < D_; d += 128)
        dot += w[(size_t)tc * D_ + d] * g_h[r * D_ + d];
    sdot[t] = dot;
    __syncthreads();
    for (int off = 64; off; off >>= 1) {
        if (t < off) sdot[t] += sdot[t + off];
        __syncthreads();
    }

    if (t == 0) {
        float m = -INFINITY, s = 0.f;
        int bi = 0x7fffffff;
        for (int blk = 0; blk < BPB; blk++) {
            int pp = b * BPB + blk;
            sm_combine(m, s, bi, g_pm[pp * 6 + l], g_ps[pp * 6 + l], g_pi[pp * 6 + l]);
        }
        float lse = m + logf(s);
        float nll = lse - sdot[0];
        int as = astarts[b];
        bool in_range = (as >= 1) && (as < T_);
        bool ptgt = (tgt >= 0 && tgt < V_) &&
                    ((g_present[b * PW + (tgt >> 5)] >> (tgt & 31)) & 1u);
        bool valid = ptgt && in_range;
        int pred = bi;
        g_rownll[r]   = valid ? nll : 0.f;
        g_rowacc[r]   = (valid && pred == tgt) ? 1.f : 0.f;
        g_rowvalid[r] = valid ? 1 : 0;
    }
}

__global__ void finalize_kernel(float* __restrict__ out) {
    if (threadIdx.x == 0) {
        float avg_loss = 0.f, avg_acc = 0.f, final_acc = 0.f;
        int nhas = 0;
        for (int l = 0; l < L_; l++) {
            float cnt = 0.f, sl = 0.f, sa = 0.f;
            for (int b = 0; b < B_; b++) {
                int r = l * B_ + b;
                cnt += (float)g_rowvalid[r];
                sl  += g_rownll[r];
                sa  += g_rowacc[r];
            }
            float denom = fmaxf(cnt, 1.f);
            float ll = sl / denom;
            float la = sa / denom;
            if (cnt > 0.f) { nhas++; avg_loss += ll; avg_acc += la; }
            if (l == L_ - 1) final_acc = la;
        }
        float nv = fmaxf((float)nhas, 1.f);
        out[0] = avg_loss / nv;
        out[1] = avg_acc / nv;
        out[2] = final_acc;
    }
}

extern "C" void kernel_launch(void* const* d_in, const int* in_sizes, int n_in,
                              void* d_out, int out_size) {
    const float* x = nullptr;
    const float* w = nullptr;
    const int* ids = nullptr;
    const int* tgts = nullptr;
    const int* astarts = nullptr;
    for (int i = 0; i < n_in; i++) {
        long sz = (long)in_sizes[i];
        if (sz == (long)L_ * B_ * T_ * D_)      x = (const float*)d_in[i];
        else if (sz == (long)V_ * D_)           w = (const float*)d_in[i];
        else if (sz == (long)B_ * T_)           ids = (const int*)d_in[i];
        else if (sz == (long)B_ * L_)           tgts = (const int*)d_in[i];
        else if (sz == (long)B_)                astarts = (const int*)d_in[i];
    }

    zero_present_kernel<<<(B_ * PW + 255) / 256, 256>>>();
    scatter_kernel<<<(B_ * T_ + 255) / 256, 256>>>(ids);
    {
        dim3 gr(NCB, B_);
        bcount_kernel<<<gr, CB>>>();
        bwrite_kernel<<<gr, CB>>>();
    }
    gather_kernel<<<R_, 256>>>(x, astarts);
    gemm_dot<<<NP, 256>>>(w);
    reduce_rows_kernel<<<R_, 128>>>(w, tgts, astarts);
    finalize_kernel<<<1, 32>>>((float*)d_out);
}